// round 2
// baseline (speedup 1.0000x reference)
#include <cuda_runtime.h>
#include <math.h>

#define NN 100000
#define EE 1600000

// ---------------- scratch (device globals; no allocation allowed) ----------------
__device__ float g_cat[NN * 128];   // [atom_x | x2] concat
__device__ float g_h[NN * 64];      // node features (h), also hl
__device__ float g_x[NN * 64];      // x = h @ lin_W
__device__ float g_aggr[NN * 64];   // scatter-add target
__device__ float g_gi[NN * 192];
__device__ float g_gh[NN * 192];
__device__ float g_deg[NN];
__device__ float g_dinv[NN];
__device__ float g_stats[152];      // [0..135] upper-tri S pairs, [136..151] column sums of edge_attr
__device__ float g_Wp[16 * 64];     // effective bond W (BN folded)
__device__ float g_bp[64];          // effective bond bias
__device__ float g_bnstats[128];    // [sum(64) | sumsq(64)]

// ---------------- utility ----------------
__global__ void zero_kernel(float* __restrict__ p, int n) {
    int i = blockIdx.x * blockDim.x + threadIdx.x;
    int s = gridDim.x * blockDim.x;
    for (; i < n; i += s) p[i] = 0.f;
}

// ---------------- degree ----------------
__global__ void deg_kernel(const int* __restrict__ rowI) {
    int s = gridDim.x * blockDim.x;
    for (int e = blockIdx.x * blockDim.x + threadIdx.x; e < EE; e += s)
        atomicAdd(&g_deg[rowI[e]], 1.0f);
}

__global__ void finalize_deg_kernel() {
    int s = gridDim.x * blockDim.x;
    for (int n = blockIdx.x * blockDim.x + threadIdx.x; n < NN; n += s) {
        float dv = g_deg[n] + 1.f;
        g_deg[n] = dv;
        g_dinv[n] = rsqrtf(dv);
    }
}

// ---------------- edge-attr second-moment stats (once; feeds analytic bond-BN) ----------------
// thread pairs: even lane handles even upper-tri pair slots, odd lane odd slots.
__global__ void __launch_bounds__(256) stats_kernel(const float* __restrict__ eattr) {
    const int tid = threadIdx.x;
    const int parity = tid & 1;
    const int pair0 = (blockIdx.x * 256 + tid) >> 1;
    const int npairs = (gridDim.x * 256) >> 1;
    float sAcc[68];
    float mAcc[8];
#pragma unroll
    for (int i = 0; i < 68; i++) sAcc[i] = 0.f;
#pragma unroll
    for (int i = 0; i < 8; i++) mAcc[i] = 0.f;

    for (int e = pair0; e < EE; e += npairs) {
        const float4* ap = reinterpret_cast<const float4*>(eattr + (size_t)e * 16);
        float4 v0 = __ldg(&ap[0]), v1 = __ldg(&ap[1]), v2 = __ldg(&ap[2]), v3 = __ldg(&ap[3]);
        float a[16];
        a[0]=v0.x; a[1]=v0.y; a[2]=v0.z; a[3]=v0.w;
        a[4]=v1.x; a[5]=v1.y; a[6]=v1.z; a[7]=v1.w;
        a[8]=v2.x; a[9]=v2.y; a[10]=v2.z; a[11]=v2.w;
        a[12]=v3.x; a[13]=v3.y; a[14]=v3.z; a[15]=v3.w;
#pragma unroll
        for (int i = 0; i < 16; i++)
            if ((i >> 3) == parity) mAcc[i & 7] += a[i];
        int p = 0;
#pragma unroll
        for (int k = 0; k < 16; k++)
#pragma unroll
            for (int l = k; l < 16; l++) {
                if ((p & 1) == parity) sAcc[p >> 1] += a[k] * a[l];
                p++;
            }
    }
    // reduce across same-parity lanes in warp (strides 16,8,4,2 preserve parity)
#pragma unroll
    for (int off = 16; off >= 2; off >>= 1) {
#pragma unroll
        for (int i = 0; i < 68; i++) sAcc[i] += __shfl_down_sync(0xffffffffu, sAcc[i], off);
#pragma unroll
        for (int i = 0; i < 8; i++) mAcc[i] += __shfl_down_sync(0xffffffffu, mAcc[i], off);
    }
    const int lane = tid & 31;
    if (lane < 2) {
#pragma unroll
        for (int i = 0; i < 68; i++) atomicAdd(&g_stats[i * 2 + lane], sAcc[i]);
#pragma unroll
        for (int i = 0; i < 8; i++) atomicAdd(&g_stats[136 + lane * 8 + i], mAcc[i]);
    }
}

// ---------------- per-layer: fold bond Linear + BatchNorm into W', b' ----------------
__global__ void bondprep_kernel(const float* __restrict__ Wl, const float* __restrict__ bl,
                                const float* __restrict__ gl, const float* __restrict__ betal) {
    const int j = threadIdx.x;  // 64 threads
    const float invE = 1.f / (float)EE;
    float w[16];
#pragma unroll
    for (int k = 0; k < 16; k++) w[k] = Wl[k * 64 + j];
    float dot_mw = 0.f;
#pragma unroll
    for (int k = 0; k < 16; k++) dot_mw += (g_stats[136 + k] * invE) * w[k];
    float quad = 0.f;
    int p = 0;
#pragma unroll
    for (int k = 0; k < 16; k++)
#pragma unroll
        for (int l = k; l < 16; l++) {
            const float s = g_stats[p++] * invE;
            quad += (k == l ? w[k] * w[l] : 2.f * w[k] * w[l]) * s;
        }
    const float b = bl[j];
    const float mean = dot_mw + b;
    const float e2 = quad + 2.f * b * dot_mw + b * b;
    const float var = e2 - mean * mean;
    const float scale = gl[j] * rsqrtf(var + 1e-6f);
#pragma unroll
    for (int k = 0; k < 16; k++) g_Wp[k * 64 + j] = w[k] * scale;
    g_bp[j] = (b - mean) * scale + betal[j];
}

// ---------------- encoder: x2 embedding sum + concat ----------------
__global__ void encoder_kernel(const float* __restrict__ ax, const int* __restrict__ feat,
                               const float* __restrict__ emb) {
    const int stride = gridDim.x * blockDim.x;
    for (int idx = blockIdx.x * blockDim.x + threadIdx.x; idx < NN * 128; idx += stride) {
        const int n = idx >> 7;
        const int c = idx & 127;
        float v;
        if (c < 64) {
            v = ax[n * 64 + c];
        } else {
            const int d = c - 64;
            v = 0.f;
#pragma unroll
            for (int f = 0; f < 9; f++) {
                const int fv = __ldg(&feat[n * 9 + f]);
                v += __ldg(&emb[(f * 16 + fv) * 64 + d]);
            }
        }
        g_cat[idx] = v;
    }
}

// ---------------- generic GEMM: C[M,NC] = A[M,K] @ B + bias ----------------
// TRANSB: Bg is (NC, K) row-major (we use B^T). Block computes 64 rows.
template <int K, int NC, bool TRANSB>
__global__ void __launch_bounds__(256) gemm_kernel(const float* __restrict__ A,
                                                   const float* __restrict__ Bg,
                                                   const float* __restrict__ bias,
                                                   float* __restrict__ C, int M) {
    constexpr int KC = 16;
    constexpr int NG = NC / 64;
    __shared__ float As[KC][68];
    __shared__ float Bs[KC][NC];
    const int tid = threadIdx.x;
    const int ty = tid >> 4;   // 0..15 -> 4 rows each
    const int tx = tid & 15;   // 0..15 -> 4 cols each (per group)
    const int rowBase = blockIdx.x * 64;

    float acc[NG][4][4];
#pragma unroll
    for (int g = 0; g < NG; g++)
#pragma unroll
        for (int i = 0; i < 4; i++)
#pragma unroll
            for (int j = 0; j < 4; j++) acc[g][i][j] = 0.f;

    for (int k0 = 0; k0 < K; k0 += KC) {
        {
            const int r = tid >> 2, q = tid & 3;
            const int gr = rowBase + r;
            float4 v = make_float4(0.f, 0.f, 0.f, 0.f);
            if (gr < M) v = *reinterpret_cast<const float4*>(&A[(size_t)gr * K + k0 + q * 4]);
            As[q * 4 + 0][r] = v.x;
            As[q * 4 + 1][r] = v.y;
            As[q * 4 + 2][r] = v.z;
            As[q * 4 + 3][r] = v.w;
        }
        if (TRANSB) {
#pragma unroll
            for (int idx = tid; idx < KC * NC; idx += 256) {
                const int n = idx / KC, kk = idx & (KC - 1);
                Bs[kk][n] = Bg[n * K + k0 + kk];
            }
        } else {
#pragma unroll
            for (int idx = tid; idx < KC * NC; idx += 256) {
                const int kk = idx / NC, n = idx - kk * NC;
                Bs[kk][n] = Bg[(k0 + kk) * NC + n];
            }
        }
        __syncthreads();
#pragma unroll
        for (int kk = 0; kk < KC; kk++) {
            const float4 a4 = *reinterpret_cast<const float4*>(&As[kk][ty * 4]);
            const float av[4] = {a4.x, a4.y, a4.z, a4.w};
#pragma unroll
            for (int g = 0; g < NG; g++) {
                const float4 b4 = *reinterpret_cast<const float4*>(&Bs[kk][g * 64 + tx * 4]);
                const float bv[4] = {b4.x, b4.y, b4.z, b4.w};
#pragma unroll
                for (int i = 0; i < 4; i++)
#pragma unroll
                    for (int j = 0; j < 4; j++) acc[g][i][j] += av[i] * bv[j];
            }
        }
        __syncthreads();
    }
#pragma unroll
    for (int i = 0; i < 4; i++) {
        const int gr = rowBase + ty * 4 + i;
        if (gr < M) {
#pragma unroll
            for (int g = 0; g < NG; g++) {
                const int cb = g * 64 + tx * 4;
                const float4 bv = *reinterpret_cast<const float4*>(&bias[cb]);
                float4 o;
                o.x = acc[g][i][0] + bv.x;
                o.y = acc[g][i][1] + bv.y;
                o.z = acc[g][i][2] + bv.z;
                o.w = acc[g][i][3] + bv.w;
                *reinterpret_cast<float4*>(&C[(size_t)gr * NC + cb]) = o;
            }
        }
    }
}

// ---------------- message + scatter: aggr[col] += norm * relu(x[row] + e_norm) ----------------
__global__ void __launch_bounds__(256) message_kernel(const int* __restrict__ rowI,
                                                      const int* __restrict__ colI,
                                                      const float* __restrict__ eattr) {
    __shared__ float Wps[16 * 64];
    __shared__ float bps[64];
    const int tid = threadIdx.x;
    for (int i = tid; i < 1024; i += 256) Wps[i] = g_Wp[i];
    if (tid < 64) bps[tid] = g_bp[tid];
    __syncthreads();
    const int grp = tid >> 6;  // 4 edges per block concurrently
    const int d = tid & 63;
    const int stride = gridDim.x * 4;
    for (int e = blockIdx.x * 4 + grp; e < EE; e += stride) {
        const int r = __ldg(&rowI[e]);
        const int c = __ldg(&colI[e]);
        const float nrm = g_dinv[r] * g_dinv[c];
        const float4* ap = reinterpret_cast<const float4*>(eattr + (size_t)e * 16);
        float acc = bps[d];
#pragma unroll
        for (int q = 0; q < 4; q++) {
            const float4 a = __ldg(&ap[q]);
            acc += a.x * Wps[(q * 4 + 0) * 64 + d];
            acc += a.y * Wps[(q * 4 + 1) * 64 + d];
            acc += a.z * Wps[(q * 4 + 2) * 64 + d];
            acc += a.w * Wps[(q * 4 + 3) * 64 + d];
        }
        float v = g_x[r * 64 + d] + acc;
        v = fmaxf(v, 0.f) * nrm;
        atomicAdd(&g_aggr[c * 64 + d], v);
    }
}

// ---------------- GRU + self term; accumulates outer-BN stats ----------------
__global__ void __launch_bounds__(256) gru_kernel(const float* __restrict__ root_l, int Mn) {
    __shared__ float ssum[64], ssq[64];
    const int tid = threadIdx.x;
    if (tid < 64) { ssum[tid] = 0.f; ssq[tid] = 0.f; }
    __syncthreads();
    const int start = blockIdx.x * 256 + tid;
    const int stride = gridDim.x * 256;  // multiple of 64 -> d constant
    const int d = start & 63;
    float ls = 0.f, ls2 = 0.f;
    for (int idx = start; idx < Mn * 64; idx += stride) {
        const int n = idx >> 6;
        const int dd = idx & 63;
        const float ir = g_gi[n * 192 + dd];
        const float iz = g_gi[n * 192 + 64 + dd];
        const float inn = g_gi[n * 192 + 128 + dd];
        const float hr = g_gh[n * 192 + dd];
        const float hz = g_gh[n * 192 + 64 + dd];
        const float hn = g_gh[n * 192 + 128 + dd];
        const float xv = g_x[idx];
        const float r = 1.f / (1.f + expf(-(ir + hr)));
        const float z = 1.f / (1.f + expf(-(iz + hz)));
        const float nn2 = tanhf(inn + r * hn);
        const float upd = (1.f - z) * nn2 + z * xv;
        const float hl = upd + fmaxf(xv + root_l[dd], 0.f) / g_deg[n];
        g_h[idx] = hl;
        ls += hl;
        ls2 += hl * hl;
    }
    atomicAdd(&ssum[d], ls);
    atomicAdd(&ssq[d], ls2);
    __syncthreads();
    if (tid < 64) {
        atomicAdd(&g_bnstats[tid], ssum[tid]);
        atomicAdd(&g_bnstats[64 + tid], ssq[tid]);
    }
}

// ---------------- outer BN apply (+ optional relu) ----------------
__global__ void __launch_bounds__(256) bn_apply_kernel(const float* __restrict__ hin,
                                                       float* __restrict__ hout,
                                                       const float* __restrict__ gamma,
                                                       const float* __restrict__ beta,
                                                       int Mn, int doRelu) {
    const int start = blockIdx.x * 256 + threadIdx.x;
    const int stride = gridDim.x * 256;
    const int d = start & 63;
    const float invN = 1.f / (float)Mn;
    const float mean = g_bnstats[d] * invN;
    const float var = g_bnstats[64 + d] * invN - mean * mean;
    const float scale = gamma[d] * rsqrtf(var + 1e-5f);
    const float shift = beta[d] - mean * scale;
    for (int idx = start; idx < Mn * 64; idx += stride) {
        float v = hin[idx] * scale + shift;
        if (doRelu) v = fmaxf(v, 0.f);
        hout[idx] = v;
    }
}

// ---------------- launch ----------------
extern "C" void kernel_launch(void* const* d_in, const int* in_sizes, int n_in,
                              void* d_out, int out_size) {
    const float* atom_x = (const float*)d_in[0];
    const int* atom_feature = (const int*)d_in[1];
    const int* edge_index = (const int*)d_in[2];
    const float* edge_attr = (const float*)d_in[3];
    const float* atom_emb = (const float*)d_in[4];
    const float* proj_W = (const float*)d_in[5];
    const float* proj_b = (const float*)d_in[6];
    const float* lin_W = (const float*)d_in[7];
    const float* lin_b = (const float*)d_in[8];
    const float* root_emb = (const float*)d_in[9];
    const float* bond_W = (const float*)d_in[10];
    const float* bond_b = (const float*)d_in[11];
    const float* bond_g = (const float*)d_in[12];
    const float* bond_beta = (const float*)d_in[13];
    const float* gru_Wih = (const float*)d_in[14];
    const float* gru_bih = (const float*)d_in[15];
    const float* gru_Whh = (const float*)d_in[16];
    const float* gru_bhh = (const float*)d_in[17];
    const float* bn_g = (const float*)d_in[18];
    const float* bn_b = (const float*)d_in[19];
    const int* rowI = edge_index;
    const int* colI = edge_index + EE;
    float* out = (float*)d_out;

    float *p_cat, *p_h, *p_x, *p_aggr, *p_gi, *p_gh, *p_deg, *p_stats, *p_bnstats;
    cudaGetSymbolAddress((void**)&p_cat, g_cat);
    cudaGetSymbolAddress((void**)&p_h, g_h);
    cudaGetSymbolAddress((void**)&p_x, g_x);
    cudaGetSymbolAddress((void**)&p_aggr, g_aggr);
    cudaGetSymbolAddress((void**)&p_gi, g_gi);
    cudaGetSymbolAddress((void**)&p_gh, g_gh);
    cudaGetSymbolAddress((void**)&p_deg, g_deg);
    cudaGetSymbolAddress((void**)&p_stats, g_stats);
    cudaGetSymbolAddress((void**)&p_bnstats, g_bnstats);

    zero_kernel<<<256, 256>>>(p_deg, NN);
    zero_kernel<<<1, 256>>>(p_stats, 152);
    deg_kernel<<<1024, 256>>>(rowI);
    finalize_deg_kernel<<<256, 256>>>();
    stats_kernel<<<296, 256>>>(edge_attr);
    encoder_kernel<<<1024, 256>>>(atom_x, atom_feature, atom_emb);
    gemm_kernel<128, 64, false><<<1563, 256>>>(p_cat, proj_W, proj_b, p_h, NN);

    for (int l = 0; l < 3; l++) {
        gemm_kernel<64, 64, false><<<1563, 256>>>(p_h, lin_W + l * 64 * 64, lin_b + l * 64, p_x, NN);
        bondprep_kernel<<<1, 64>>>(bond_W + l * 16 * 64, bond_b + l * 64, bond_g + l * 64,
                                   bond_beta + l * 64);
        zero_kernel<<<512, 256>>>(p_aggr, NN * 64);
        message_kernel<<<1184, 256>>>(rowI, colI, edge_attr);
        gemm_kernel<64, 192, true><<<1563, 256>>>(p_aggr, gru_Wih + l * 192 * 64,
                                                  gru_bih + l * 192, p_gi, NN);
        gemm_kernel<64, 192, true><<<1563, 256>>>(p_x, gru_Whh + l * 192 * 64,
                                                  gru_bhh + l * 192, p_gh, NN);
        zero_kernel<<<1, 128>>>(p_bnstats, 128);
        gru_kernel<<<512, 256>>>(root_emb + l * 64, NN);
        bn_apply_kernel<<<512, 256>>>(p_h, (l == 2) ? out : p_h, bn_g + l * 64, bn_b + l * 64,
                                      NN, (l < 2) ? 1 : 0);
    }
}

// round 3
// speedup vs baseline: 1.3852x; 1.3852x over previous
#include <cuda_runtime.h>
#include <math.h>

#define NN 100000
#define EE 1600000

// ---------------- scratch (device globals; no allocation allowed) ----------------
__device__ float g_cat[NN * 128];   // [atom_x | x2] concat
__device__ float g_h[NN * 64];      // node features (h), also hl
__device__ float g_x[NN * 64];      // x = h @ lin_W
__device__ float g_aggr[NN * 64];   // gather target
__device__ float g_gi[NN * 192];
__device__ float g_gh[NN * 192];
__device__ float g_deg[NN];
__device__ float g_dinv[NN];
__device__ float g_stats[152];      // [0..135] upper-tri S pairs, [136..151] column sums of edge_attr
__device__ float g_Wp[16 * 64];     // effective bond W (BN folded)
__device__ float g_bp[64];          // effective bond bias
__device__ float g_bnstats[128];    // [sum(64) | sumsq(64)]
// CSR by destination (col)
__device__ int g_cnt[NN];
__device__ int g_coff[NN + 1];
__device__ int g_cur[NN];
__device__ int g_bsum[128];
__device__ int g_erow[EE];
__device__ int g_eidx[EE];

// ---------------- utility ----------------
__global__ void zero_kernel(float* __restrict__ p, int n) {
    int i = blockIdx.x * blockDim.x + threadIdx.x;
    int s = gridDim.x * blockDim.x;
    for (; i < n; i += s) p[i] = 0.f;
}
__global__ void zeroi_kernel(int* __restrict__ p, int n) {
    int i = blockIdx.x * blockDim.x + threadIdx.x;
    int s = gridDim.x * blockDim.x;
    for (; i < n; i += s) p[i] = 0;
}

// ---------------- degree (by row) ----------------
__global__ void deg_kernel(const int* __restrict__ rowI) {
    int s = gridDim.x * blockDim.x;
    for (int e = blockIdx.x * blockDim.x + threadIdx.x; e < EE; e += s)
        atomicAdd(&g_deg[rowI[e]], 1.0f);
}
__global__ void finalize_deg_kernel() {
    int s = gridDim.x * blockDim.x;
    for (int n = blockIdx.x * blockDim.x + threadIdx.x; n < NN; n += s) {
        float dv = g_deg[n] + 1.f;
        g_deg[n] = dv;
        g_dinv[n] = rsqrtf(dv);
    }
}

// ---------------- CSR-by-destination build ----------------
__global__ void count_col_kernel(const int* __restrict__ colI) {
    int s = gridDim.x * blockDim.x;
    for (int e = blockIdx.x * blockDim.x + threadIdx.x; e < EE; e += s)
        atomicAdd(&g_cnt[colI[e]], 1);
}

__global__ void __launch_bounds__(256) scan1_kernel() {  // grid=ceil(NN/1024), block=256
    __shared__ int wsum[8];
    const int b = blockIdx.x;
    const int base = b * 1024;
    const int t = threadIdx.x;
    const int lane = t & 31, w = t >> 5;
    int v[4];
    const int idx0 = base + t * 4;
#pragma unroll
    for (int i = 0; i < 4; i++) {
        const int ii = idx0 + i;
        v[i] = (ii < NN) ? g_cnt[ii] : 0;
    }
    const int local = v[0] + v[1] + v[2] + v[3];
    int x = local;
#pragma unroll
    for (int off = 1; off < 32; off <<= 1) {
        int y = __shfl_up_sync(0xffffffffu, x, off);
        if (lane >= off) x += y;
    }
    if (lane == 31) wsum[w] = x;
    __syncthreads();
    if (t == 0) {
        int s = 0;
#pragma unroll
        for (int i = 0; i < 8; i++) { int tmp = wsum[i]; wsum[i] = s; s += tmp; }
        g_bsum[b] = s;
    }
    __syncthreads();
    int run = x - local + wsum[w];
#pragma unroll
    for (int i = 0; i < 4; i++) {
        const int ii = idx0 + i;
        if (ii < NN) g_coff[ii] = run;
        run += v[i];
    }
}

__global__ void scan2_kernel(int nb) {  // scan block sums (nb ~ 98), single thread
    if (threadIdx.x == 0 && blockIdx.x == 0) {
        int s = 0;
        for (int i = 0; i < nb; i++) { int t = g_bsum[i]; g_bsum[i] = s; s += t; }
    }
}

__global__ void scan3_kernel() {
    int i = blockIdx.x * blockDim.x + threadIdx.x;
    int s = gridDim.x * blockDim.x;
    for (; i < NN; i += s) {
        const int vv = g_coff[i] + g_bsum[i >> 10];
        g_coff[i] = vv;
        g_cur[i] = vv;
    }
    if (blockIdx.x == 0 && threadIdx.x == 0) g_coff[NN] = EE;
}

__global__ void fill_kernel(const int* __restrict__ rowI, const int* __restrict__ colI) {
    int s = gridDim.x * blockDim.x;
    for (int e = blockIdx.x * blockDim.x + threadIdx.x; e < EE; e += s) {
        const int c = colI[e];
        const int pos = atomicAdd(&g_cur[c], 1);
        g_erow[pos] = rowI[e];
        g_eidx[pos] = e;
    }
}

// ---------------- edge-attr second-moment stats (once; feeds analytic bond-BN) ----------------
__global__ void __launch_bounds__(256) stats_kernel(const float* __restrict__ eattr) {
    const int tid = threadIdx.x;
    const int parity = tid & 1;
    const int pair0 = (blockIdx.x * 256 + tid) >> 1;
    const int npairs = (gridDim.x * 256) >> 1;
    float sAcc[68];
    float mAcc[8];
#pragma unroll
    for (int i = 0; i < 68; i++) sAcc[i] = 0.f;
#pragma unroll
    for (int i = 0; i < 8; i++) mAcc[i] = 0.f;

    for (int e = pair0; e < EE; e += npairs) {
        const float4* ap = reinterpret_cast<const float4*>(eattr + (size_t)e * 16);
        float4 v0 = __ldg(&ap[0]), v1 = __ldg(&ap[1]), v2 = __ldg(&ap[2]), v3 = __ldg(&ap[3]);
        float a[16];
        a[0]=v0.x; a[1]=v0.y; a[2]=v0.z; a[3]=v0.w;
        a[4]=v1.x; a[5]=v1.y; a[6]=v1.z; a[7]=v1.w;
        a[8]=v2.x; a[9]=v2.y; a[10]=v2.z; a[11]=v2.w;
        a[12]=v3.x; a[13]=v3.y; a[14]=v3.z; a[15]=v3.w;
#pragma unroll
        for (int i = 0; i < 16; i++)
            if ((i >> 3) == parity) mAcc[i & 7] += a[i];
        int p = 0;
#pragma unroll
        for (int k = 0; k < 16; k++)
#pragma unroll
            for (int l = k; l < 16; l++) {
                if ((p & 1) == parity) sAcc[p >> 1] += a[k] * a[l];
                p++;
            }
    }
#pragma unroll
    for (int off = 16; off >= 2; off >>= 1) {
#pragma unroll
        for (int i = 0; i < 68; i++) sAcc[i] += __shfl_down_sync(0xffffffffu, sAcc[i], off);
#pragma unroll
        for (int i = 0; i < 8; i++) mAcc[i] += __shfl_down_sync(0xffffffffu, mAcc[i], off);
    }
    const int lane = tid & 31;
    if (lane < 2) {
#pragma unroll
        for (int i = 0; i < 68; i++) atomicAdd(&g_stats[i * 2 + lane], sAcc[i]);
#pragma unroll
        for (int i = 0; i < 8; i++) atomicAdd(&g_stats[136 + lane * 8 + i], mAcc[i]);
    }
}

// ---------------- per-layer: fold bond Linear + BatchNorm into W', b' ----------------
__global__ void bondprep_kernel(const float* __restrict__ Wl, const float* __restrict__ bl,
                                const float* __restrict__ gl, const float* __restrict__ betal) {
    const int j = threadIdx.x;  // 64 threads
    const float invE = 1.f / (float)EE;
    float w[16];
#pragma unroll
    for (int k = 0; k < 16; k++) w[k] = Wl[k * 64 + j];
    float dot_mw = 0.f;
#pragma unroll
    for (int k = 0; k < 16; k++) dot_mw += (g_stats[136 + k] * invE) * w[k];
    float quad = 0.f;
    int p = 0;
#pragma unroll
    for (int k = 0; k < 16; k++)
#pragma unroll
        for (int l = k; l < 16; l++) {
            const float s = g_stats[p++] * invE;
            quad += (k == l ? w[k] * w[l] : 2.f * w[k] * w[l]) * s;
        }
    const float b = bl[j];
    const float mean = dot_mw + b;
    const float e2 = quad + 2.f * b * dot_mw + b * b;
    const float var = e2 - mean * mean;
    const float scale = gl[j] * rsqrtf(var + 1e-6f);
#pragma unroll
    for (int k = 0; k < 16; k++) g_Wp[k * 64 + j] = w[k] * scale;
    g_bp[j] = (b - mean) * scale + betal[j];
}

// ---------------- encoder: x2 embedding sum + concat ----------------
__global__ void encoder_kernel(const float* __restrict__ ax, const int* __restrict__ feat,
                               const float* __restrict__ emb) {
    const int stride = gridDim.x * blockDim.x;
    for (int idx = blockIdx.x * blockDim.x + threadIdx.x; idx < NN * 128; idx += stride) {
        const int n = idx >> 7;
        const int c = idx & 127;
        float v;
        if (c < 64) {
            v = ax[n * 64 + c];
        } else {
            const int d = c - 64;
            v = 0.f;
#pragma unroll
            for (int f = 0; f < 9; f++) {
                const int fv = __ldg(&feat[n * 9 + f]);
                v += __ldg(&emb[(f * 16 + fv) * 64 + d]);
            }
        }
        g_cat[idx] = v;
    }
}

// ---------------- generic GEMM: C[M,NC] = A[M,K] @ B + bias ----------------
template <int K, int NC, bool TRANSB>
__global__ void __launch_bounds__(256) gemm_kernel(const float* __restrict__ A,
                                                   const float* __restrict__ Bg,
                                                   const float* __restrict__ bias,
                                                   float* __restrict__ C, int M) {
    constexpr int KC = 16;
    constexpr int NG = NC / 64;
    __shared__ float As[KC][68];
    __shared__ float Bs[KC][NC];
    const int tid = threadIdx.x;
    const int ty = tid >> 4;
    const int tx = tid & 15;
    const int rowBase = blockIdx.x * 64;

    float acc[NG][4][4];
#pragma unroll
    for (int g = 0; g < NG; g++)
#pragma unroll
        for (int i = 0; i < 4; i++)
#pragma unroll
            for (int j = 0; j < 4; j++) acc[g][i][j] = 0.f;

    for (int k0 = 0; k0 < K; k0 += KC) {
        {
            const int r = tid >> 2, q = tid & 3;
            const int gr = rowBase + r;
            float4 v = make_float4(0.f, 0.f, 0.f, 0.f);
            if (gr < M) v = *reinterpret_cast<const float4*>(&A[(size_t)gr * K + k0 + q * 4]);
            As[q * 4 + 0][r] = v.x;
            As[q * 4 + 1][r] = v.y;
            As[q * 4 + 2][r] = v.z;
            As[q * 4 + 3][r] = v.w;
        }
        if (TRANSB) {
#pragma unroll
            for (int idx = tid; idx < KC * NC; idx += 256) {
                const int n = idx / KC, kk = idx & (KC - 1);
                Bs[kk][n] = Bg[n * K + k0 + kk];
            }
        } else {
#pragma unroll
            for (int idx = tid; idx < KC * NC; idx += 256) {
                const int kk = idx / NC, n = idx - kk * NC;
                Bs[kk][n] = Bg[(k0 + kk) * NC + n];
            }
        }
        __syncthreads();
#pragma unroll
        for (int kk = 0; kk < KC; kk++) {
            const float4 a4 = *reinterpret_cast<const float4*>(&As[kk][ty * 4]);
            const float av[4] = {a4.x, a4.y, a4.z, a4.w};
#pragma unroll
            for (int g = 0; g < NG; g++) {
                const float4 b4 = *reinterpret_cast<const float4*>(&Bs[kk][g * 64 + tx * 4]);
                const float bv[4] = {b4.x, b4.y, b4.z, b4.w};
#pragma unroll
                for (int i = 0; i < 4; i++)
#pragma unroll
                    for (int j = 0; j < 4; j++) acc[g][i][j] += av[i] * bv[j];
            }
        }
        __syncthreads();
    }
#pragma unroll
    for (int i = 0; i < 4; i++) {
        const int gr = rowBase + ty * 4 + i;
        if (gr < M) {
#pragma unroll
            for (int g = 0; g < NG; g++) {
                const int cb = g * 64 + tx * 4;
                const float4 bv = *reinterpret_cast<const float4*>(&bias[cb]);
                float4 o;
                o.x = acc[g][i][0] + bv.x;
                o.y = acc[g][i][1] + bv.y;
                o.z = acc[g][i][2] + bv.z;
                o.w = acc[g][i][3] + bv.w;
                *reinterpret_cast<float4*>(&C[(size_t)gr * NC + cb]) = o;
            }
        }
    }
}

// ---------------- CSR gather: aggr[n] = sum over in-edges of norm*relu(x[row]+e_bond) ----
// 16 threads per node, each owns 4 dims; W' in registers (64 regs/thread).
__global__ void __launch_bounds__(256) gather_kernel(const float* __restrict__ eattr) {
    const int tid = threadIdx.x;
    const int t = tid & 15;
    const int nloc = tid >> 4;
    const int n = blockIdx.x * 16 + nloc;
    float4 wreg[16];
#pragma unroll
    for (int k = 0; k < 16; k++)
        wreg[k] = *reinterpret_cast<const float4*>(&g_Wp[k * 64 + t * 4]);
    const float4 bb = *reinterpret_cast<const float4*>(&g_bp[t * 4]);
    if (n >= NN) return;
    const int jb = g_coff[n];
    const int je = g_coff[n + 1];
    const float dn = g_dinv[n];
    float4 acc = make_float4(0.f, 0.f, 0.f, 0.f);
    for (int j = jb; j < je; j++) {
        const int e = __ldg(&g_eidx[j]);
        const int r = __ldg(&g_erow[j]);
        const float nrm = dn * __ldg(&g_dinv[r]);
        const float4* ap = reinterpret_cast<const float4*>(eattr + (size_t)e * 16);
        float4 m = bb;
#pragma unroll
        for (int q = 0; q < 4; q++) {
            const float4 a = __ldg(&ap[q]);
            const float4 w0 = wreg[4 * q + 0];
            const float4 w1 = wreg[4 * q + 1];
            const float4 w2 = wreg[4 * q + 2];
            const float4 w3 = wreg[4 * q + 3];
            m.x = fmaf(a.x, w0.x, fmaf(a.y, w1.x, fmaf(a.z, w2.x, fmaf(a.w, w3.x, m.x))));
            m.y = fmaf(a.x, w0.y, fmaf(a.y, w1.y, fmaf(a.z, w2.y, fmaf(a.w, w3.y, m.y))));
            m.z = fmaf(a.x, w0.z, fmaf(a.y, w1.z, fmaf(a.z, w2.z, fmaf(a.w, w3.z, m.z))));
            m.w = fmaf(a.x, w0.w, fmaf(a.y, w1.w, fmaf(a.z, w2.w, fmaf(a.w, w3.w, m.w))));
        }
        const float4 xv = __ldg(reinterpret_cast<const float4*>(&g_x[(size_t)r * 64 + t * 4]));
        acc.x = fmaf(nrm, fmaxf(m.x + xv.x, 0.f), acc.x);
        acc.y = fmaf(nrm, fmaxf(m.y + xv.y, 0.f), acc.y);
        acc.z = fmaf(nrm, fmaxf(m.z + xv.z, 0.f), acc.z);
        acc.w = fmaf(nrm, fmaxf(m.w + xv.w, 0.f), acc.w);
    }
    *reinterpret_cast<float4*>(&g_aggr[(size_t)n * 64 + t * 4]) = acc;
}

// ---------------- GRU + self term; accumulates outer-BN stats ----------------
__global__ void __launch_bounds__(256) gru_kernel(const float* __restrict__ root_l, int Mn) {
    __shared__ float ssum[64], ssq[64];
    const int tid = threadIdx.x;
    if (tid < 64) { ssum[tid] = 0.f; ssq[tid] = 0.f; }
    __syncthreads();
    const int start = blockIdx.x * 256 + tid;
    const int stride = gridDim.x * 256;
    const int d = start & 63;
    float ls = 0.f, ls2 = 0.f;
    for (int idx = start; idx < Mn * 64; idx += stride) {
        const int n = idx >> 6;
        const int dd = idx & 63;
        const float ir = g_gi[n * 192 + dd];
        const float iz = g_gi[n * 192 + 64 + dd];
        const float inn = g_gi[n * 192 + 128 + dd];
        const float hr = g_gh[n * 192 + dd];
        const float hz = g_gh[n * 192 + 64 + dd];
        const float hn = g_gh[n * 192 + 128 + dd];
        const float xv = g_x[idx];
        const float r = 1.f / (1.f + expf(-(ir + hr)));
        const float z = 1.f / (1.f + expf(-(iz + hz)));
        const float nn2 = tanhf(inn + r * hn);
        const float upd = (1.f - z) * nn2 + z * xv;
        const float hl = upd + fmaxf(xv + root_l[dd], 0.f) / g_deg[n];
        g_h[idx] = hl;
        ls += hl;
        ls2 += hl * hl;
    }
    atomicAdd(&ssum[d], ls);
    atomicAdd(&ssq[d], ls2);
    __syncthreads();
    if (tid < 64) {
        atomicAdd(&g_bnstats[tid], ssum[tid]);
        atomicAdd(&g_bnstats[64 + tid], ssq[tid]);
    }
}

// ---------------- outer BN apply (+ optional relu) ----------------
__global__ void __launch_bounds__(256) bn_apply_kernel(const float* __restrict__ hin,
                                                       float* __restrict__ hout,
                                                       const float* __restrict__ gamma,
                                                       const float* __restrict__ beta,
                                                       int Mn, int doRelu) {
    const int start = blockIdx.x * 256 + threadIdx.x;
    const int stride = gridDim.x * 256;
    const int d = start & 63;
    const float invN = 1.f / (float)Mn;
    const float mean = g_bnstats[d] * invN;
    const float var = g_bnstats[64 + d] * invN - mean * mean;
    const float scale = gamma[d] * rsqrtf(var + 1e-5f);
    const float shift = beta[d] - mean * scale;
    for (int idx = start; idx < Mn * 64; idx += stride) {
        float v = hin[idx] * scale + shift;
        if (doRelu) v = fmaxf(v, 0.f);
        hout[idx] = v;
    }
}

// ---------------- launch ----------------
extern "C" void kernel_launch(void* const* d_in, const int* in_sizes, int n_in,
                              void* d_out, int out_size) {
    const float* atom_x = (const float*)d_in[0];
    const int* atom_feature = (const int*)d_in[1];
    const int* edge_index = (const int*)d_in[2];
    const float* edge_attr = (const float*)d_in[3];
    const float* atom_emb = (const float*)d_in[4];
    const float* proj_W = (const float*)d_in[5];
    const float* proj_b = (const float*)d_in[6];
    const float* lin_W = (const float*)d_in[7];
    const float* lin_b = (const float*)d_in[8];
    const float* root_emb = (const float*)d_in[9];
    const float* bond_W = (const float*)d_in[10];
    const float* bond_b = (const float*)d_in[11];
    const float* bond_g = (const float*)d_in[12];
    const float* bond_beta = (const float*)d_in[13];
    const float* gru_Wih = (const float*)d_in[14];
    const float* gru_bih = (const float*)d_in[15];
    const float* gru_Whh = (const float*)d_in[16];
    const float* gru_bhh = (const float*)d_in[17];
    const float* bn_g = (const float*)d_in[18];
    const float* bn_b = (const float*)d_in[19];
    const int* rowI = edge_index;
    const int* colI = edge_index + EE;
    float* out = (float*)d_out;

    float *p_cat, *p_h, *p_x, *p_aggr, *p_gi, *p_gh, *p_deg, *p_stats, *p_bnstats;
    int* p_cnt;
    cudaGetSymbolAddress((void**)&p_cat, g_cat);
    cudaGetSymbolAddress((void**)&p_h, g_h);
    cudaGetSymbolAddress((void**)&p_x, g_x);
    cudaGetSymbolAddress((void**)&p_aggr, g_aggr);
    cudaGetSymbolAddress((void**)&p_gi, g_gi);
    cudaGetSymbolAddress((void**)&p_gh, g_gh);
    cudaGetSymbolAddress((void**)&p_deg, g_deg);
    cudaGetSymbolAddress((void**)&p_stats, g_stats);
    cudaGetSymbolAddress((void**)&p_bnstats, g_bnstats);
    cudaGetSymbolAddress((void**)&p_cnt, g_cnt);

    const int nScanBlocks = (NN + 1023) / 1024;

    // graph-structure prep (once per launch)
    zero_kernel<<<256, 256>>>(p_deg, NN);
    zero_kernel<<<1, 256>>>(p_stats, 152);
    zeroi_kernel<<<256, 256>>>(p_cnt, NN);
    deg_kernel<<<1024, 256>>>(rowI);
    finalize_deg_kernel<<<256, 256>>>();
    count_col_kernel<<<1024, 256>>>(colI);
    scan1_kernel<<<nScanBlocks, 256>>>();
    scan2_kernel<<<1, 32>>>(nScanBlocks);
    scan3_kernel<<<256, 256>>>();
    fill_kernel<<<1024, 256>>>(rowI, colI);
    stats_kernel<<<296, 256>>>(edge_attr);

    encoder_kernel<<<1024, 256>>>(atom_x, atom_feature, atom_emb);
    gemm_kernel<128, 64, false><<<1563, 256>>>(p_cat, proj_W, proj_b, p_h, NN);

    for (int l = 0; l < 3; l++) {
        gemm_kernel<64, 64, false><<<1563, 256>>>(p_h, lin_W + l * 64 * 64, lin_b + l * 64, p_x, NN);
        bondprep_kernel<<<1, 64>>>(bond_W + l * 16 * 64, bond_b + l * 64, bond_g + l * 64,
                                   bond_beta + l * 64);
        gather_kernel<<<(NN + 15) / 16, 256>>>(edge_attr);
        gemm_kernel<64, 192, true><<<1563, 256>>>(p_aggr, gru_Wih + l * 192 * 64,
                                                  gru_bih + l * 192, p_gi, NN);
        gemm_kernel<64, 192, true><<<1563, 256>>>(p_x, gru_Whh + l * 192 * 64,
                                                  gru_bhh + l * 192, p_gh, NN);
        zero_kernel<<<1, 128>>>(p_bnstats, 128);
        gru_kernel<<<512, 256>>>(root_emb + l * 64, NN);
        bn_apply_kernel<<<512, 256>>>(p_h, (l == 2) ? out : p_h, bn_g + l * 64, bn_b + l * 64,
                                      NN, (l < 2) ? 1 : 0);
    }
}

// round 4
// speedup vs baseline: 1.5792x; 1.1401x over previous
#include <cuda_runtime.h>
#include <math.h>

#define NN 100000
#define EE 1600000

// ---------------- scratch (device globals) ----------------
__device__ float g_cat[NN * 128];
__device__ float g_h[NN * 64];
__device__ float g_x[NN * 64];
__device__ float g_aggr[NN * 64];
__device__ float g_deg[NN];
__device__ float g_dinv[NN];
__device__ float g_stats[152];
__device__ float g_Wp[16 * 64];
__device__ float g_bp[64];
__device__ float g_bnstats[128];
// CSR by destination (col), with permuted payloads
__device__ int g_cntR[NN];
__device__ int g_cnt[NN];
__device__ int g_coff[NN + 1];
__device__ int g_cur[NN];
__device__ int g_bsum[128];
__device__ int g_erow[EE];
__device__ float g_nrm[EE];
__device__ float g_eattrp[EE * 16];

// ---------------- utility ----------------
__global__ void zero_kernel(float* __restrict__ p, int n) {
    int i = blockIdx.x * blockDim.x + threadIdx.x;
    int s = gridDim.x * blockDim.x;
    for (; i < n; i += s) p[i] = 0.f;
}
__global__ void zeroi_kernel(int* __restrict__ p, int n) {
    int i = blockIdx.x * blockDim.x + threadIdx.x;
    int s = gridDim.x * blockDim.x;
    for (; i < n; i += s) p[i] = 0;
}

// ---------------- combined degree(row) + count(col) ----------------
__global__ void count_kernel(const int* __restrict__ rowI, const int* __restrict__ colI) {
    int s = gridDim.x * blockDim.x;
    for (int e = blockIdx.x * blockDim.x + threadIdx.x; e < EE; e += s) {
        atomicAdd(&g_cntR[rowI[e]], 1);
        atomicAdd(&g_cnt[colI[e]], 1);
    }
}
__global__ void finalize_deg_kernel() {
    int s = gridDim.x * blockDim.x;
    for (int n = blockIdx.x * blockDim.x + threadIdx.x; n < NN; n += s) {
        float dv = (float)g_cntR[n] + 1.f;
        g_deg[n] = dv;
        g_dinv[n] = rsqrtf(dv);
    }
}

// ---------------- CSR scan ----------------
__global__ void __launch_bounds__(256) scan1_kernel() {
    __shared__ int wsum[8];
    const int b = blockIdx.x;
    const int base = b * 1024;
    const int t = threadIdx.x;
    const int lane = t & 31, w = t >> 5;
    int v[4];
    const int idx0 = base + t * 4;
#pragma unroll
    for (int i = 0; i < 4; i++) {
        const int ii = idx0 + i;
        v[i] = (ii < NN) ? g_cnt[ii] : 0;
    }
    const int local = v[0] + v[1] + v[2] + v[3];
    int x = local;
#pragma unroll
    for (int off = 1; off < 32; off <<= 1) {
        int y = __shfl_up_sync(0xffffffffu, x, off);
        if (lane >= off) x += y;
    }
    if (lane == 31) wsum[w] = x;
    __syncthreads();
    if (t == 0) {
        int s = 0;
#pragma unroll
        for (int i = 0; i < 8; i++) { int tmp = wsum[i]; wsum[i] = s; s += tmp; }
        g_bsum[b] = s;
    }
    __syncthreads();
    int run = x - local + wsum[w];
#pragma unroll
    for (int i = 0; i < 4; i++) {
        const int ii = idx0 + i;
        if (ii < NN) g_coff[ii] = run;
        run += v[i];
    }
}
__global__ void scan2_kernel(int nb) {
    if (threadIdx.x == 0 && blockIdx.x == 0) {
        int s = 0;
        for (int i = 0; i < nb; i++) { int t = g_bsum[i]; g_bsum[i] = s; s += t; }
    }
}
__global__ void scan3_kernel() {
    int i = blockIdx.x * blockDim.x + threadIdx.x;
    int s = gridDim.x * blockDim.x;
    for (; i < NN; i += s) {
        const int vv = g_coff[i] + g_bsum[i >> 10];
        g_coff[i] = vv;
        g_cur[i] = vv;
    }
    if (blockIdx.x == 0 && threadIdx.x == 0) g_coff[NN] = EE;
}

// ---------------- fill: permute payloads into CSR order ----------------
__global__ void fill_kernel(const int* __restrict__ rowI, const int* __restrict__ colI,
                            const float* __restrict__ eattr) {
    int s = gridDim.x * blockDim.x;
    for (int e = blockIdx.x * blockDim.x + threadIdx.x; e < EE; e += s) {
        const int c = colI[e];
        const int r = rowI[e];
        const int pos = atomicAdd(&g_cur[c], 1);
        g_erow[pos] = r;
        g_nrm[pos] = g_dinv[r] * g_dinv[c];
        const float4* src = reinterpret_cast<const float4*>(eattr + (size_t)e * 16);
        float4* dst = reinterpret_cast<float4*>(g_eattrp + (size_t)pos * 16);
        dst[0] = __ldg(&src[0]);
        dst[1] = __ldg(&src[1]);
        dst[2] = __ldg(&src[2]);
        dst[3] = __ldg(&src[3]);
    }
}

// ---------------- edge-attr second-moment stats ----------------
__global__ void __launch_bounds__(256) stats_kernel(const float* __restrict__ eattr) {
    const int tid = threadIdx.x;
    const int parity = tid & 1;
    const int pair0 = (blockIdx.x * 256 + tid) >> 1;
    const int npairs = (gridDim.x * 256) >> 1;
    float sAcc[68];
    float mAcc[8];
#pragma unroll
    for (int i = 0; i < 68; i++) sAcc[i] = 0.f;
#pragma unroll
    for (int i = 0; i < 8; i++) mAcc[i] = 0.f;

    for (int e = pair0; e < EE; e += npairs) {
        const float4* ap = reinterpret_cast<const float4*>(eattr + (size_t)e * 16);
        float4 v0 = __ldg(&ap[0]), v1 = __ldg(&ap[1]), v2 = __ldg(&ap[2]), v3 = __ldg(&ap[3]);
        float a[16];
        a[0]=v0.x; a[1]=v0.y; a[2]=v0.z; a[3]=v0.w;
        a[4]=v1.x; a[5]=v1.y; a[6]=v1.z; a[7]=v1.w;
        a[8]=v2.x; a[9]=v2.y; a[10]=v2.z; a[11]=v2.w;
        a[12]=v3.x; a[13]=v3.y; a[14]=v3.z; a[15]=v3.w;
#pragma unroll
        for (int i = 0; i < 16; i++)
            if ((i >> 3) == parity) mAcc[i & 7] += a[i];
        int p = 0;
#pragma unroll
        for (int k = 0; k < 16; k++)
#pragma unroll
            for (int l = k; l < 16; l++) {
                if ((p & 1) == parity) sAcc[p >> 1] += a[k] * a[l];
                p++;
            }
    }
#pragma unroll
    for (int off = 16; off >= 2; off >>= 1) {
#pragma unroll
        for (int i = 0; i < 68; i++) sAcc[i] += __shfl_down_sync(0xffffffffu, sAcc[i], off);
#pragma unroll
        for (int i = 0; i < 8; i++) mAcc[i] += __shfl_down_sync(0xffffffffu, mAcc[i], off);
    }
    const int lane = tid & 31;
    if (lane < 2) {
#pragma unroll
        for (int i = 0; i < 68; i++) atomicAdd(&g_stats[i * 2 + lane], sAcc[i]);
#pragma unroll
        for (int i = 0; i < 8; i++) atomicAdd(&g_stats[136 + lane * 8 + i], mAcc[i]);
    }
}

// ---------------- fold bond Linear + BatchNorm into W', b' ----------------
__global__ void bondprep_kernel(const float* __restrict__ Wl, const float* __restrict__ bl,
                                const float* __restrict__ gl, const float* __restrict__ betal) {
    const int j = threadIdx.x;
    const float invE = 1.f / (float)EE;
    float w[16];
#pragma unroll
    for (int k = 0; k < 16; k++) w[k] = Wl[k * 64 + j];
    float dot_mw = 0.f;
#pragma unroll
    for (int k = 0; k < 16; k++) dot_mw += (g_stats[136 + k] * invE) * w[k];
    float quad = 0.f;
    int p = 0;
#pragma unroll
    for (int k = 0; k < 16; k++)
#pragma unroll
        for (int l = k; l < 16; l++) {
            const float s = g_stats[p++] * invE;
            quad += (k == l ? w[k] * w[l] : 2.f * w[k] * w[l]) * s;
        }
    const float b = bl[j];
    const float mean = dot_mw + b;
    const float e2 = quad + 2.f * b * dot_mw + b * b;
    const float var = e2 - mean * mean;
    const float scale = gl[j] * rsqrtf(var + 1e-6f);
#pragma unroll
    for (int k = 0; k < 16; k++) g_Wp[k * 64 + j] = w[k] * scale;
    g_bp[j] = (b - mean) * scale + betal[j];
}

// ---------------- encoder ----------------
__global__ void encoder_kernel(const float* __restrict__ ax, const int* __restrict__ feat,
                               const float* __restrict__ emb) {
    const int stride = gridDim.x * blockDim.x;
    for (int idx = blockIdx.x * blockDim.x + threadIdx.x; idx < NN * 128; idx += stride) {
        const int n = idx >> 7;
        const int c = idx & 127;
        float v;
        if (c < 64) {
            v = ax[n * 64 + c];
        } else {
            const int d = c - 64;
            v = 0.f;
#pragma unroll
            for (int f = 0; f < 9; f++) {
                const int fv = __ldg(&feat[n * 9 + f]);
                v += __ldg(&emb[(f * 16 + fv) * 64 + d]);
            }
        }
        g_cat[idx] = v;
    }
}

// ---------------- GEMM: C[M,64] = A[M,K] @ B + bias ----------------
template <int K>
__global__ void __launch_bounds__(256) gemm_kernel(const float* __restrict__ A,
                                                   const float* __restrict__ Bg,
                                                   const float* __restrict__ bias,
                                                   float* __restrict__ C, int M) {
    constexpr int KC = 16;
    __shared__ float As[KC][68];
    __shared__ float Bs[KC][64];
    const int tid = threadIdx.x;
    const int ty = tid >> 4;
    const int tx = tid & 15;
    const int rowBase = blockIdx.x * 64;

    float acc[4][4];
#pragma unroll
    for (int i = 0; i < 4; i++)
#pragma unroll
        for (int j = 0; j < 4; j++) acc[i][j] = 0.f;

    for (int k0 = 0; k0 < K; k0 += KC) {
        {
            const int r = tid >> 2, q = tid & 3;
            const int gr = rowBase + r;
            float4 v = make_float4(0.f, 0.f, 0.f, 0.f);
            if (gr < M) v = *reinterpret_cast<const float4*>(&A[(size_t)gr * K + k0 + q * 4]);
            As[q * 4 + 0][r] = v.x;
            As[q * 4 + 1][r] = v.y;
            As[q * 4 + 2][r] = v.z;
            As[q * 4 + 3][r] = v.w;
        }
#pragma unroll
        for (int idx = tid; idx < KC * 64; idx += 256) {
            const int kk = idx >> 6, n = idx & 63;
            Bs[kk][n] = Bg[(k0 + kk) * 64 + n];
        }
        __syncthreads();
#pragma unroll
        for (int kk = 0; kk < KC; kk++) {
            const float4 a4 = *reinterpret_cast<const float4*>(&As[kk][ty * 4]);
            const float av[4] = {a4.x, a4.y, a4.z, a4.w};
            const float4 b4 = *reinterpret_cast<const float4*>(&Bs[kk][tx * 4]);
            const float bv[4] = {b4.x, b4.y, b4.z, b4.w};
#pragma unroll
            for (int i = 0; i < 4; i++)
#pragma unroll
                for (int j = 0; j < 4; j++) acc[i][j] += av[i] * bv[j];
        }
        __syncthreads();
    }
#pragma unroll
    for (int i = 0; i < 4; i++) {
        const int gr = rowBase + ty * 4 + i;
        if (gr < M) {
            const float4 bv = *reinterpret_cast<const float4*>(&bias[tx * 4]);
            float4 o;
            o.x = acc[i][0] + bv.x;
            o.y = acc[i][1] + bv.y;
            o.z = acc[i][2] + bv.z;
            o.w = acc[i][3] + bv.w;
            *reinterpret_cast<float4*>(&C[(size_t)gr * 64 + tx * 4]) = o;
        }
    }
}

// ---------------- CSR gather ----------------
__global__ void __launch_bounds__(256) gather_kernel() {
    const int tid = threadIdx.x;
    const int t = tid & 15;
    const int nloc = tid >> 4;
    const int n = blockIdx.x * 16 + nloc;
    float4 wreg[16];
#pragma unroll
    for (int k = 0; k < 16; k++)
        wreg[k] = *reinterpret_cast<const float4*>(&g_Wp[k * 64 + t * 4]);
    const float4 bb = *reinterpret_cast<const float4*>(&g_bp[t * 4]);
    if (n >= NN) return;
    const int jb = g_coff[n];
    const int je = g_coff[n + 1];
    float4 acc = make_float4(0.f, 0.f, 0.f, 0.f);
    for (int j = jb; j < je; j++) {
        const int r = __ldg(&g_erow[j]);
        const float nrm = __ldg(&g_nrm[j]);
        const float4* ap = reinterpret_cast<const float4*>(g_eattrp + (size_t)j * 16);
        float4 m = bb;
#pragma unroll
        for (int q = 0; q < 4; q++) {
            const float4 a = __ldg(&ap[q]);
            const float4 w0 = wreg[4 * q + 0];
            const float4 w1 = wreg[4 * q + 1];
            const float4 w2 = wreg[4 * q + 2];
            const float4 w3 = wreg[4 * q + 3];
            m.x = fmaf(a.x, w0.x, fmaf(a.y, w1.x, fmaf(a.z, w2.x, fmaf(a.w, w3.x, m.x))));
            m.y = fmaf(a.x, w0.y, fmaf(a.y, w1.y, fmaf(a.z, w2.y, fmaf(a.w, w3.y, m.y))));
            m.z = fmaf(a.x, w0.z, fmaf(a.y, w1.z, fmaf(a.z, w2.z, fmaf(a.w, w3.z, m.z))));
            m.w = fmaf(a.x, w0.w, fmaf(a.y, w1.w, fmaf(a.z, w2.w, fmaf(a.w, w3.w, m.w))));
        }
        const float4 xv = __ldg(reinterpret_cast<const float4*>(&g_x[(size_t)r * 64 + t * 4]));
        acc.x = fmaf(nrm, fmaxf(m.x + xv.x, 0.f), acc.x);
        acc.y = fmaf(nrm, fmaxf(m.y + xv.y, 0.f), acc.y);
        acc.z = fmaf(nrm, fmaxf(m.z + xv.z, 0.f), acc.z);
        acc.w = fmaf(nrm, fmaxf(m.w + xv.w, 0.f), acc.w);
    }
    *reinterpret_cast<float4*>(&g_aggr[(size_t)n * 64 + t * 4]) = acc;
}

// ---------------- fused GRU: gi+gh GEMMs in regs + elementwise + BN stats ------------
// block: 256 threads (tx 0..15 over d-slots, ty 0..15 over 4-row groups), 64-row tile
__global__ void __launch_bounds__(256, 1) grufused_kernel(
    const float* __restrict__ Wih, const float* __restrict__ bih,
    const float* __restrict__ Whh, const float* __restrict__ bhh,
    const float* __restrict__ root, int M) {
    extern __shared__ float smem[];
    float4* Wih4 = reinterpret_cast<float4*>(smem);            // 192*17 float4
    float4* Whh4 = Wih4 + 192 * 17;                            // 192*17 float4
    float* Aag = reinterpret_cast<float*>(Whh4 + 192 * 17);    // 64*64
    float* Ax = Aag + 64 * 64;                                 // 64*64
    float* ssum = Ax + 64 * 64;                                // 64
    float* ssq = ssum + 64;                                    // 64

    const int tid = threadIdx.x;
    const int tx = tid & 15;
    const int ty = tid >> 4;
    const int rowBase = blockIdx.x * 64;

    const float4* Wih_g = reinterpret_cast<const float4*>(Wih);
    const float4* Whh_g = reinterpret_cast<const float4*>(Whh);
#pragma unroll
    for (int idx = tid; idx < 192 * 16; idx += 256) {
        const int j = idx >> 4, k4 = idx & 15;
        Wih4[j * 17 + k4] = __ldg(&Wih_g[idx]);
        Whh4[j * 17 + k4] = __ldg(&Whh_g[idx]);
    }
#pragma unroll
    for (int idx = tid; idx < 64 * 16; idx += 256) {
        const int r = idx >> 4;
        const int gr = rowBase + r;
        float4 va = make_float4(0.f, 0.f, 0.f, 0.f);
        float4 vx = make_float4(0.f, 0.f, 0.f, 0.f);
        if (gr < M) {
            va = *reinterpret_cast<const float4*>(&g_aggr[(size_t)gr * 64 + (idx & 15) * 4]);
            vx = *reinterpret_cast<const float4*>(&g_x[(size_t)gr * 64 + (idx & 15) * 4]);
        }
        reinterpret_cast<float4*>(Aag)[idx] = va;
        reinterpret_cast<float4*>(Ax)[idx] = vx;
    }
    if (tid < 64) { ssum[tid] = 0.f; ssq[tid] = 0.f; }
    __syncthreads();

    float acc_i[4][4][3];
    float acc_h[4][4][3];
#pragma unroll
    for (int ri = 0; ri < 4; ri++)
#pragma unroll
        for (int di = 0; di < 4; di++)
#pragma unroll
            for (int g = 0; g < 3; g++) { acc_i[ri][di][g] = 0.f; acc_h[ri][di][g] = 0.f; }

    const float4* Aag4 = reinterpret_cast<const float4*>(Aag);
    const float4* Ax4 = reinterpret_cast<const float4*>(Ax);
    for (int k4 = 0; k4 < 16; k4++) {
        float4 aag[4], axx[4];
#pragma unroll
        for (int ri = 0; ri < 4; ri++) {
            aag[ri] = Aag4[(ty * 4 + ri) * 16 + k4];
            axx[ri] = Ax4[(ty * 4 + ri) * 16 + k4];
        }
#pragma unroll
        for (int g = 0; g < 3; g++)
#pragma unroll
            for (int di = 0; di < 4; di++) {
                const int j = g * 64 + di * 16 + tx;
                const float4 wi = Wih4[j * 17 + k4];
                const float4 wh = Whh4[j * 17 + k4];
#pragma unroll
                for (int ri = 0; ri < 4; ri++) {
                    acc_i[ri][di][g] = fmaf(aag[ri].x, wi.x,
                        fmaf(aag[ri].y, wi.y, fmaf(aag[ri].z, wi.z,
                        fmaf(aag[ri].w, wi.w, acc_i[ri][di][g]))));
                    acc_h[ri][di][g] = fmaf(axx[ri].x, wh.x,
                        fmaf(axx[ri].y, wh.y, fmaf(axx[ri].z, wh.z,
                        fmaf(axx[ri].w, wh.w, acc_h[ri][di][g]))));
                }
            }
    }

    float ls[4] = {0.f, 0.f, 0.f, 0.f};
    float ls2[4] = {0.f, 0.f, 0.f, 0.f};
#pragma unroll
    for (int ri = 0; ri < 4; ri++) {
        const int row = rowBase + ty * 4 + ri;
        if (row < M) {
            const float dg = __ldg(&g_deg[row]);
#pragma unroll
            for (int di = 0; di < 4; di++) {
                const int d = di * 16 + tx;
                const float ir = acc_i[ri][di][0] + __ldg(&bih[d]);
                const float iz = acc_i[ri][di][1] + __ldg(&bih[64 + d]);
                const float inn = acc_i[ri][di][2] + __ldg(&bih[128 + d]);
                const float hr = acc_h[ri][di][0] + __ldg(&bhh[d]);
                const float hz = acc_h[ri][di][1] + __ldg(&bhh[64 + d]);
                const float hn = acc_h[ri][di][2] + __ldg(&bhh[128 + d]);
                const float xv = Ax[(ty * 4 + ri) * 64 + d];
                const float r = 1.f / (1.f + expf(-(ir + hr)));
                const float z = 1.f / (1.f + expf(-(iz + hz)));
                const float nn2 = tanhf(inn + r * hn);
                const float upd = (1.f - z) * nn2 + z * xv;
                const float hl = upd + fmaxf(xv + __ldg(&root[d]), 0.f) / dg;
                g_h[(size_t)row * 64 + d] = hl;
                ls[di] += hl;
                ls2[di] += hl * hl;
            }
        }
    }
#pragma unroll
    for (int di = 0; di < 4; di++) {
        atomicAdd(&ssum[di * 16 + tx], ls[di]);
        atomicAdd(&ssq[di * 16 + tx], ls2[di]);
    }
    __syncthreads();
    if (tid < 64) {
        atomicAdd(&g_bnstats[tid], ssum[tid]);
        atomicAdd(&g_bnstats[64 + tid], ssq[tid]);
    }
}

// ---------------- outer BN apply ----------------
__global__ void __launch_bounds__(256) bn_apply_kernel(const float* __restrict__ hin,
                                                       float* __restrict__ hout,
                                                       const float* __restrict__ gamma,
                                                       const float* __restrict__ beta,
                                                       int Mn, int doRelu) {
    const int start = blockIdx.x * 256 + threadIdx.x;
    const int stride = gridDim.x * 256;
    const int d = start & 63;
    const float invN = 1.f / (float)Mn;
    const float mean = g_bnstats[d] * invN;
    const float var = g_bnstats[64 + d] * invN - mean * mean;
    const float scale = gamma[d] * rsqrtf(var + 1e-5f);
    const float shift = beta[d] - mean * scale;
    for (int idx = start; idx < Mn * 64; idx += stride) {
        float v = hin[idx] * scale + shift;
        if (doRelu) v = fmaxf(v, 0.f);
        hout[idx] = v;
    }
}

// ---------------- launch ----------------
extern "C" void kernel_launch(void* const* d_in, const int* in_sizes, int n_in,
                              void* d_out, int out_size) {
    const float* atom_x = (const float*)d_in[0];
    const int* atom_feature = (const int*)d_in[1];
    const int* edge_index = (const int*)d_in[2];
    const float* edge_attr = (const float*)d_in[3];
    const float* atom_emb = (const float*)d_in[4];
    const float* proj_W = (const float*)d_in[5];
    const float* proj_b = (const float*)d_in[6];
    const float* lin_W = (const float*)d_in[7];
    const float* lin_b = (const float*)d_in[8];
    const float* root_emb = (const float*)d_in[9];
    const float* bond_W = (const float*)d_in[10];
    const float* bond_b = (const float*)d_in[11];
    const float* bond_g = (const float*)d_in[12];
    const float* bond_beta = (const float*)d_in[13];
    const float* gru_Wih = (const float*)d_in[14];
    const float* gru_bih = (const float*)d_in[15];
    const float* gru_Whh = (const float*)d_in[16];
    const float* gru_bhh = (const float*)d_in[17];
    const float* bn_g = (const float*)d_in[18];
    const float* bn_b = (const float*)d_in[19];
    const int* rowI = edge_index;
    const int* colI = edge_index + EE;
    float* out = (float*)d_out;

    float *p_cat, *p_h, *p_x, *p_deg, *p_stats, *p_bnstats;
    int *p_cnt, *p_cntR;
    cudaGetSymbolAddress((void**)&p_cat, g_cat);
    cudaGetSymbolAddress((void**)&p_h, g_h);
    cudaGetSymbolAddress((void**)&p_x, g_x);
    cudaGetSymbolAddress((void**)&p_deg, g_deg);
    cudaGetSymbolAddress((void**)&p_stats, g_stats);
    cudaGetSymbolAddress((void**)&p_bnstats, g_bnstats);
    cudaGetSymbolAddress((void**)&p_cnt, g_cnt);
    cudaGetSymbolAddress((void**)&p_cntR, g_cntR);

    static int smemSet = 0;
    const int gruSmem = (2 * 192 * 17 * 16) + (2 * 64 * 64 * 4) + 2 * 64 * 4;
    if (!smemSet) {
        cudaFuncSetAttribute(grufused_kernel, cudaFuncAttributeMaxDynamicSharedMemorySize,
                             gruSmem);
        smemSet = 1;
    }

    const int nScanBlocks = (NN + 1023) / 1024;

    zero_kernel<<<1, 256>>>(p_stats, 152);
    zeroi_kernel<<<256, 256>>>(p_cnt, NN);
    zeroi_kernel<<<256, 256>>>(p_cntR, NN);
    count_kernel<<<1024, 256>>>(rowI, colI);
    finalize_deg_kernel<<<256, 256>>>();
    scan1_kernel<<<nScanBlocks, 256>>>();
    scan2_kernel<<<1, 32>>>(nScanBlocks);
    scan3_kernel<<<256, 256>>>();
    fill_kernel<<<1024, 256>>>(rowI, colI, edge_attr);
    stats_kernel<<<296, 256>>>(edge_attr);

    encoder_kernel<<<1024, 256>>>(atom_x, atom_feature, atom_emb);
    gemm_kernel<128><<<1563, 256>>>(p_cat, proj_W, proj_b, p_h, NN);

    for (int l = 0; l < 3; l++) {
        gemm_kernel<64><<<1563, 256>>>(p_h, lin_W + l * 64 * 64, lin_b + l * 64, p_x, NN);
        bondprep_kernel<<<1, 64>>>(bond_W + l * 16 * 64, bond_b + l * 64, bond_g + l * 64,
                                   bond_beta + l * 64);
        gather_kernel<<<(NN + 15) / 16, 256>>>();
        zero_kernel<<<1, 128>>>(p_bnstats, 128);
        grufused_kernel<<<1563, 256, gruSmem>>>(gru_Wih + l * 192 * 64, gru_bih + l * 192,
                                                gru_Whh + l * 192 * 64, gru_bhh + l * 192,
                                                root_emb + l * 64, NN);
        bn_apply_kernel<<<512, 256>>>(p_h, (l == 2) ? out : p_h, bn_g + l * 64, bn_b + l * 64,
                                      NN, (l < 2) ? 1 : 0);
    }
}

// round 5
// speedup vs baseline: 1.6878x; 1.0688x over previous
#include <cuda_runtime.h>
#include <math.h>

#define NN 100000
#define EE 1600000

// ---------------- scratch (device globals) ----------------
__device__ float g_cat[NN * 128];
__device__ float g_h[NN * 64];
__device__ float g_x[NN * 64];
__device__ float g_aggr[NN * 64];
__device__ float g_deg[NN];
__device__ float g_dinv[NN];
__device__ float g_stats[152];
__device__ float g_Wp[16 * 64];
__device__ float g_bp[64];
__device__ float g_bnstats[128];
// packed tf32 hi/lo W fragments: [layer][which][nt=24][ks=8][t=32][4]
__device__ float g_wpack[3 * 2 * 24 * 8 * 32 * 4];
// CSR by destination (col), with permuted payloads
__device__ int g_cntR[NN];
__device__ int g_cnt[NN];
__device__ int g_coff[NN + 1];
__device__ int g_cur[NN];
__device__ int g_bsum[128];
__device__ int g_erow[EE];
__device__ float g_nrm[EE];
__device__ float g_eattrp[EE * 16];

// ---------------- tf32 helpers ----------------
__device__ __forceinline__ unsigned f2tf32(float v) {
    unsigned r;
    asm("cvt.rna.tf32.f32 %0, %1;" : "=r"(r) : "f"(v));
    return r;
}
__device__ __forceinline__ void mma_tf32(float* c, unsigned a0, unsigned a1, unsigned a2,
                                         unsigned a3, unsigned b0, unsigned b1) {
    asm("mma.sync.aligned.m16n8k8.row.col.f32.tf32.tf32.f32 "
        "{%0,%1,%2,%3}, {%4,%5,%6,%7}, {%8,%9}, {%0,%1,%2,%3};"
        : "+f"(c[0]), "+f"(c[1]), "+f"(c[2]), "+f"(c[3])
        : "r"(a0), "r"(a1), "r"(a2), "r"(a3), "r"(b0), "r"(b1));
}

// ---------------- utility ----------------
__global__ void zero_kernel(float* __restrict__ p, int n) {
    int i = blockIdx.x * blockDim.x + threadIdx.x;
    int s = gridDim.x * blockDim.x;
    for (; i < n; i += s) p[i] = 0.f;
}
__global__ void zeroi_kernel(int* __restrict__ p, int n) {
    int i = blockIdx.x * blockDim.x + threadIdx.x;
    int s = gridDim.x * blockDim.x;
    for (; i < n; i += s) p[i] = 0;
}

// ---------------- pack W hi/lo fragments (all layers, both GRU mats) ----------------
__global__ void packw_kernel(const float* __restrict__ Wih, const float* __restrict__ Whh) {
    // grid: 3*2*24 blocks of 256 (8 ks * 32 lanes)
    const int l = blockIdx.x / 48;
    const int rem = blockIdx.x % 48;
    const int which = rem / 24;
    const int nt = rem % 24;
    const float* W = (which == 0 ? Wih : Whh) + (size_t)l * 192 * 64;
    const int ks = threadIdx.x >> 5;
    const int t = threadIdx.x & 31;
    const int g = t >> 2, tg = t & 3;
    const int n = nt * 8 + g;
    const int k0 = ks * 8 + tg;
    const float w0 = W[n * 64 + k0];
    const float w4 = W[n * 64 + k0 + 4];
    const unsigned h0 = f2tf32(w0), h4 = f2tf32(w4);
    const float l0 = w0 - __uint_as_float(h0), l4 = w4 - __uint_as_float(h4);
    float4 o;
    o.x = __uint_as_float(h0);
    o.y = __uint_as_float(h4);
    o.z = __uint_as_float(f2tf32(l0));
    o.w = __uint_as_float(f2tf32(l4));
    const size_t base = (((size_t)(l * 2 + which) * 24 + nt) * 8 + ks) * 32 + t;
    *reinterpret_cast<float4*>(&g_wpack[base * 4]) = o;
}

// ---------------- combined degree(row) + count(col) ----------------
__global__ void count_kernel(const int* __restrict__ rowI, const int* __restrict__ colI) {
    int s = gridDim.x * blockDim.x;
    for (int e = blockIdx.x * blockDim.x + threadIdx.x; e < EE; e += s) {
        atomicAdd(&g_cntR[rowI[e]], 1);
        atomicAdd(&g_cnt[colI[e]], 1);
    }
}
__global__ void finalize_deg_kernel() {
    int s = gridDim.x * blockDim.x;
    for (int n = blockIdx.x * blockDim.x + threadIdx.x; n < NN; n += s) {
        float dv = (float)g_cntR[n] + 1.f;
        g_deg[n] = dv;
        g_dinv[n] = rsqrtf(dv);
    }
}

// ---------------- CSR scan ----------------
__global__ void __launch_bounds__(256) scan1_kernel() {
    __shared__ int wsum[8];
    const int b = blockIdx.x;
    const int base = b * 1024;
    const int t = threadIdx.x;
    const int lane = t & 31, w = t >> 5;
    int v[4];
    const int idx0 = base + t * 4;
#pragma unroll
    for (int i = 0; i < 4; i++) {
        const int ii = idx0 + i;
        v[i] = (ii < NN) ? g_cnt[ii] : 0;
    }
    const int local = v[0] + v[1] + v[2] + v[3];
    int x = local;
#pragma unroll
    for (int off = 1; off < 32; off <<= 1) {
        int y = __shfl_up_sync(0xffffffffu, x, off);
        if (lane >= off) x += y;
    }
    if (lane == 31) wsum[w] = x;
    __syncthreads();
    if (t == 0) {
        int s = 0;
#pragma unroll
        for (int i = 0; i < 8; i++) { int tmp = wsum[i]; wsum[i] = s; s += tmp; }
        g_bsum[b] = s;
    }
    __syncthreads();
    int run = x - local + wsum[w];
#pragma unroll
    for (int i = 0; i < 4; i++) {
        const int ii = idx0 + i;
        if (ii < NN) g_coff[ii] = run;
        run += v[i];
    }
}
__global__ void scan2_kernel(int nb) {
    if (threadIdx.x == 0 && blockIdx.x == 0) {
        int s = 0;
        for (int i = 0; i < nb; i++) { int t = g_bsum[i]; g_bsum[i] = s; s += t; }
    }
}
__global__ void scan3_kernel() {
    int i = blockIdx.x * blockDim.x + threadIdx.x;
    int s = gridDim.x * blockDim.x;
    for (; i < NN; i += s) {
        const int vv = g_coff[i] + g_bsum[i >> 10];
        g_coff[i] = vv;
        g_cur[i] = vv;
    }
    if (blockIdx.x == 0 && threadIdx.x == 0) g_coff[NN] = EE;
}

// ---------------- fill: permute payloads into CSR order ----------------
__global__ void fill_kernel(const int* __restrict__ rowI, const int* __restrict__ colI,
                            const float* __restrict__ eattr) {
    int s = gridDim.x * blockDim.x;
    for (int e = blockIdx.x * blockDim.x + threadIdx.x; e < EE; e += s) {
        const int c = colI[e];
        const int r = rowI[e];
        const int pos = atomicAdd(&g_cur[c], 1);
        g_erow[pos] = r;
        g_nrm[pos] = g_dinv[r] * g_dinv[c];
        const float4* src = reinterpret_cast<const float4*>(eattr + (size_t)e * 16);
        float4* dst = reinterpret_cast<float4*>(g_eattrp + (size_t)pos * 16);
        dst[0] = __ldg(&src[0]);
        dst[1] = __ldg(&src[1]);
        dst[2] = __ldg(&src[2]);
        dst[3] = __ldg(&src[3]);
    }
}

// ---------------- edge-attr second-moment stats ----------------
__global__ void __launch_bounds__(256) stats_kernel(const float* __restrict__ eattr) {
    const int tid = threadIdx.x;
    const int parity = tid & 1;
    const int pair0 = (blockIdx.x * 256 + tid) >> 1;
    const int npairs = (gridDim.x * 256) >> 1;
    float sAcc[68];
    float mAcc[8];
#pragma unroll
    for (int i = 0; i < 68; i++) sAcc[i] = 0.f;
#pragma unroll
    for (int i = 0; i < 8; i++) mAcc[i] = 0.f;

    for (int e = pair0; e < EE; e += npairs) {
        const float4* ap = reinterpret_cast<const float4*>(eattr + (size_t)e * 16);
        float4 v0 = __ldg(&ap[0]), v1 = __ldg(&ap[1]), v2 = __ldg(&ap[2]), v3 = __ldg(&ap[3]);
        float a[16];
        a[0]=v0.x; a[1]=v0.y; a[2]=v0.z; a[3]=v0.w;
        a[4]=v1.x; a[5]=v1.y; a[6]=v1.z; a[7]=v1.w;
        a[8]=v2.x; a[9]=v2.y; a[10]=v2.z; a[11]=v2.w;
        a[12]=v3.x; a[13]=v3.y; a[14]=v3.z; a[15]=v3.w;
#pragma unroll
        for (int i = 0; i < 16; i++)
            if ((i >> 3) == parity) mAcc[i & 7] += a[i];
        int p = 0;
#pragma unroll
        for (int k = 0; k < 16; k++)
#pragma unroll
            for (int l = k; l < 16; l++) {
                if ((p & 1) == parity) sAcc[p >> 1] += a[k] * a[l];
                p++;
            }
    }
#pragma unroll
    for (int off = 16; off >= 2; off >>= 1) {
#pragma unroll
        for (int i = 0; i < 68; i++) sAcc[i] += __shfl_down_sync(0xffffffffu, sAcc[i], off);
#pragma unroll
        for (int i = 0; i < 8; i++) mAcc[i] += __shfl_down_sync(0xffffffffu, mAcc[i], off);
    }
    const int lane = tid & 31;
    if (lane < 2) {
#pragma unroll
        for (int i = 0; i < 68; i++) atomicAdd(&g_stats[i * 2 + lane], sAcc[i]);
#pragma unroll
        for (int i = 0; i < 8; i++) atomicAdd(&g_stats[136 + lane * 8 + i], mAcc[i]);
    }
}

// ---------------- fold bond Linear + BatchNorm into W', b' ----------------
__global__ void bondprep_kernel(const float* __restrict__ Wl, const float* __restrict__ bl,
                                const float* __restrict__ gl, const float* __restrict__ betal) {
    const int j = threadIdx.x;
    const float invE = 1.f / (float)EE;
    float w[16];
#pragma unroll
    for (int k = 0; k < 16; k++) w[k] = Wl[k * 64 + j];
    float dot_mw = 0.f;
#pragma unroll
    for (int k = 0; k < 16; k++) dot_mw += (g_stats[136 + k] * invE) * w[k];
    float quad = 0.f;
    int p = 0;
#pragma unroll
    for (int k = 0; k < 16; k++)
#pragma unroll
        for (int l = k; l < 16; l++) {
            const float s = g_stats[p++] * invE;
            quad += (k == l ? w[k] * w[l] : 2.f * w[k] * w[l]) * s;
        }
    const float b = bl[j];
    const float mean = dot_mw + b;
    const float e2 = quad + 2.f * b * dot_mw + b * b;
    const float var = e2 - mean * mean;
    const float scale = gl[j] * rsqrtf(var + 1e-6f);
#pragma unroll
    for (int k = 0; k < 16; k++) g_Wp[k * 64 + j] = w[k] * scale;
    g_bp[j] = (b - mean) * scale + betal[j];
}

// ---------------- encoder ----------------
__global__ void encoder_kernel(const float* __restrict__ ax, const int* __restrict__ feat,
                               const float* __restrict__ emb) {
    const int stride = gridDim.x * blockDim.x;
    for (int idx = blockIdx.x * blockDim.x + threadIdx.x; idx < NN * 128; idx += stride) {
        const int n = idx >> 7;
        const int c = idx & 127;
        float v;
        if (c < 64) {
            v = ax[n * 64 + c];
        } else {
            const int d = c - 64;
            v = 0.f;
#pragma unroll
            for (int f = 0; f < 9; f++) {
                const int fv = __ldg(&feat[n * 9 + f]);
                v += __ldg(&emb[(f * 16 + fv) * 64 + d]);
            }
        }
        g_cat[idx] = v;
    }
}

// ---------------- GEMM: C[M,64] = A[M,K] @ B + bias ----------------
template <int K>
__global__ void __launch_bounds__(256) gemm_kernel(const float* __restrict__ A,
                                                   const float* __restrict__ Bg,
                                                   const float* __restrict__ bias,
                                                   float* __restrict__ C, int M) {
    constexpr int KC = 16;
    __shared__ float As[KC][68];
    __shared__ float Bs[KC][64];
    const int tid = threadIdx.x;
    const int ty = tid >> 4;
    const int tx = tid & 15;
    const int rowBase = blockIdx.x * 64;

    float acc[4][4];
#pragma unroll
    for (int i = 0; i < 4; i++)
#pragma unroll
        for (int j = 0; j < 4; j++) acc[i][j] = 0.f;

    for (int k0 = 0; k0 < K; k0 += KC) {
        {
            const int r = tid >> 2, q = tid & 3;
            const int gr = rowBase + r;
            float4 v = make_float4(0.f, 0.f, 0.f, 0.f);
            if (gr < M) v = *reinterpret_cast<const float4*>(&A[(size_t)gr * K + k0 + q * 4]);
            As[q * 4 + 0][r] = v.x;
            As[q * 4 + 1][r] = v.y;
            As[q * 4 + 2][r] = v.z;
            As[q * 4 + 3][r] = v.w;
        }
#pragma unroll
        for (int idx = tid; idx < KC * 64; idx += 256) {
            const int kk = idx >> 6, n = idx & 63;
            Bs[kk][n] = Bg[(k0 + kk) * 64 + n];
        }
        __syncthreads();
#pragma unroll
        for (int kk = 0; kk < KC; kk++) {
            const float4 a4 = *reinterpret_cast<const float4*>(&As[kk][ty * 4]);
            const float av[4] = {a4.x, a4.y, a4.z, a4.w};
            const float4 b4 = *reinterpret_cast<const float4*>(&Bs[kk][tx * 4]);
            const float bv[4] = {b4.x, b4.y, b4.z, b4.w};
#pragma unroll
            for (int i = 0; i < 4; i++)
#pragma unroll
                for (int j = 0; j < 4; j++) acc[i][j] += av[i] * bv[j];
        }
        __syncthreads();
    }
#pragma unroll
    for (int i = 0; i < 4; i++) {
        const int gr = rowBase + ty * 4 + i;
        if (gr < M) {
            const float4 bv = *reinterpret_cast<const float4*>(&bias[tx * 4]);
            float4 o;
            o.x = acc[i][0] + bv.x;
            o.y = acc[i][1] + bv.y;
            o.z = acc[i][2] + bv.z;
            o.w = acc[i][3] + bv.w;
            *reinterpret_cast<float4*>(&C[(size_t)gr * 64 + tx * 4]) = o;
        }
    }
}

// ---------------- CSR gather ----------------
__global__ void __launch_bounds__(256) gather_kernel() {
    const int tid = threadIdx.x;
    const int t = tid & 15;
    const int nloc = tid >> 4;
    const int n = blockIdx.x * 16 + nloc;
    float4 wreg[16];
#pragma unroll
    for (int k = 0; k < 16; k++)
        wreg[k] = *reinterpret_cast<const float4*>(&g_Wp[k * 64 + t * 4]);
    const float4 bb = *reinterpret_cast<const float4*>(&g_bp[t * 4]);
    if (n >= NN) return;
    const int jb = g_coff[n];
    const int je = g_coff[n + 1];
    float4 acc = make_float4(0.f, 0.f, 0.f, 0.f);
    for (int j = jb; j < je; j++) {
        const int r = __ldg(&g_erow[j]);
        const float nrm = __ldg(&g_nrm[j]);
        const float4* ap = reinterpret_cast<const float4*>(g_eattrp + (size_t)j * 16);
        float4 m = bb;
#pragma unroll
        for (int q = 0; q < 4; q++) {
            const float4 a = __ldg(&ap[q]);
            const float4 w0 = wreg[4 * q + 0];
            const float4 w1 = wreg[4 * q + 1];
            const float4 w2 = wreg[4 * q + 2];
            const float4 w3 = wreg[4 * q + 3];
            m.x = fmaf(a.x, w0.x, fmaf(a.y, w1.x, fmaf(a.z, w2.x, fmaf(a.w, w3.x, m.x))));
            m.y = fmaf(a.x, w0.y, fmaf(a.y, w1.y, fmaf(a.z, w2.y, fmaf(a.w, w3.y, m.y))));
            m.z = fmaf(a.x, w0.z, fmaf(a.y, w1.z, fmaf(a.z, w2.z, fmaf(a.w, w3.z, m.z))));
            m.w = fmaf(a.x, w0.w, fmaf(a.y, w1.w, fmaf(a.z, w2.w, fmaf(a.w, w3.w, m.w))));
        }
        const float4 xv = __ldg(reinterpret_cast<const float4*>(&g_x[(size_t)r * 64 + t * 4]));
        acc.x = fmaf(nrm, fmaxf(m.x + xv.x, 0.f), acc.x);
        acc.y = fmaf(nrm, fmaxf(m.y + xv.y, 0.f), acc.y);
        acc.z = fmaf(nrm, fmaxf(m.z + xv.z, 0.f), acc.z);
        acc.w = fmaf(nrm, fmaxf(m.w + xv.w, 0.f), acc.w);
    }
    *reinterpret_cast<float4*>(&g_aggr[(size_t)n * 64 + t * 4]) = acc;
}

// ---------------- fused GRU with tf32 HMMA (3xTF32) ----------------
// smem: Aag[64*68] | Ax[64*68] | Sgi[64*196] | Sgh[64*196] | ssum[64] | ssq[64]
__global__ void __launch_bounds__(256, 1) grumma_kernel(
    const float* __restrict__ bih, const float* __restrict__ bhh,
    const float* __restrict__ root, const float* __restrict__ wpackI,
    const float* __restrict__ wpackH, int M) {
    extern __shared__ float smem[];
    float* Aag = smem;                 // 64*68
    float* Ax = Aag + 64 * 68;         // 64*68
    float* Sgi = Ax + 64 * 68;         // 64*196
    float* Sgh = Sgi + 64 * 196;       // 64*196
    float* ssum = Sgh + 64 * 196;      // 64
    float* ssq = ssum + 64;            // 64

    const int tid = threadIdx.x;
    const int w = tid >> 5;
    const int lane = tid & 31;
    const int rowBase = blockIdx.x * 64;

    // load A tiles
#pragma unroll
    for (int idx = tid; idx < 64 * 16; idx += 256) {
        const int r = idx >> 4;
        const int c4 = idx & 15;
        const int gr = rowBase + r;
        float4 va = make_float4(0.f, 0.f, 0.f, 0.f);
        float4 vx = make_float4(0.f, 0.f, 0.f, 0.f);
        if (gr < M) {
            va = *reinterpret_cast<const float4*>(&g_aggr[(size_t)gr * 64 + c4 * 4]);
            vx = *reinterpret_cast<const float4*>(&g_x[(size_t)gr * 64 + c4 * 4]);
        }
        *reinterpret_cast<float4*>(&Aag[r * 68 + c4 * 4]) = va;
        *reinterpret_cast<float4*>(&Ax[r * 68 + c4 * 4]) = vx;
    }
    if (tid < 64) { ssum[tid] = 0.f; ssq[tid] = 0.f; }
    __syncthreads();

    const int mrow = w & 3;           // m-tile (16 rows each)
    const int ntbase = (w >> 2) * 12; // 12 n-tiles per warp
    const int g = lane >> 2, tg = lane & 3;

    // ---- two GEMMs: A (from smem) x Wpack -> S ----
#pragma unroll
    for (int which = 0; which < 2; which++) {
        const float* A = (which == 0) ? Aag : Ax;
        const float* wp = (which == 0) ? wpackI : wpackH;
        float* S = (which == 0) ? Sgi : Sgh;

        float accs[12][4];
#pragma unroll
        for (int j = 0; j < 12; j++)
#pragma unroll
            for (int q = 0; q < 4; q++) accs[j][q] = 0.f;

#pragma unroll
        for (int ks = 0; ks < 8; ks++) {
            const int k0 = ks * 8;
            const float a0f = A[(mrow * 16 + g) * 68 + k0 + tg];
            const float a1f = A[(mrow * 16 + g + 8) * 68 + k0 + tg];
            const float a2f = A[(mrow * 16 + g) * 68 + k0 + tg + 4];
            const float a3f = A[(mrow * 16 + g + 8) * 68 + k0 + tg + 4];
            unsigned ah[4], al[4];
            const float af[4] = {a0f, a1f, a2f, a3f};
#pragma unroll
            for (int q = 0; q < 4; q++) {
                ah[q] = f2tf32(af[q]);
                al[q] = f2tf32(af[q] - __uint_as_float(ah[q]));
            }
#pragma unroll
            for (int j = 0; j < 12; j++) {
                const int nt = ntbase + j;
                const float4 b =
                    __ldg(reinterpret_cast<const float4*>(&wp[(((size_t)nt * 8 + ks) * 32 + lane) * 4]));
                const unsigned bh0 = __float_as_uint(b.x);
                const unsigned bh4 = __float_as_uint(b.y);
                const unsigned bl0 = __float_as_uint(b.z);
                const unsigned bl4 = __float_as_uint(b.w);
                mma_tf32(accs[j], ah[0], ah[1], ah[2], ah[3], bh0, bh4);
                mma_tf32(accs[j], al[0], al[1], al[2], al[3], bh0, bh4);
                mma_tf32(accs[j], ah[0], ah[1], ah[2], ah[3], bl0, bl4);
            }
        }
        // store C tiles to smem
#pragma unroll
        for (int j = 0; j < 12; j++) {
            const int n0 = (ntbase + j) * 8;
            const int r0 = mrow * 16 + g;
            *reinterpret_cast<float2*>(&S[r0 * 196 + n0 + tg * 2]) =
                make_float2(accs[j][0], accs[j][1]);
            *reinterpret_cast<float2*>(&S[(r0 + 8) * 196 + n0 + tg * 2]) =
                make_float2(accs[j][2], accs[j][3]);
        }
    }
    __syncthreads();

    // ---- epilogue: GRU elementwise + self term + BN stats ----
    const int tx = tid & 15;
    const int ty = tid >> 4;
    float ls[4] = {0.f, 0.f, 0.f, 0.f};
    float ls2[4] = {0.f, 0.f, 0.f, 0.f};
#pragma unroll
    for (int ri = 0; ri < 4; ri++) {
        const int r = ty * 4 + ri;
        const int row = rowBase + r;
        if (row < M) {
            const float dg = __ldg(&g_deg[row]);
#pragma unroll
            for (int di = 0; di < 4; di++) {
                const int d = di * 16 + tx;
                const float ir = Sgi[r * 196 + d] + __ldg(&bih[d]);
                const float iz = Sgi[r * 196 + 64 + d] + __ldg(&bih[64 + d]);
                const float inn = Sgi[r * 196 + 128 + d] + __ldg(&bih[128 + d]);
                const float hr = Sgh[r * 196 + d] + __ldg(&bhh[d]);
                const float hz = Sgh[r * 196 + 64 + d] + __ldg(&bhh[64 + d]);
                const float hn = Sgh[r * 196 + 128 + d] + __ldg(&bhh[128 + d]);
                const float xv = Ax[r * 68 + d];
                const float rr = 1.f / (1.f + expf(-(ir + hr)));
                const float z = 1.f / (1.f + expf(-(iz + hz)));
                const float nn2 = tanhf(inn + rr * hn);
                const float upd = (1.f - z) * nn2 + z * xv;
                const float hl = upd + fmaxf(xv + __ldg(&root[d]), 0.f) / dg;
                g_h[(size_t)row * 64 + d] = hl;
                ls[di] += hl;
                ls2[di] += hl * hl;
            }
        }
    }
#pragma unroll
    for (int di = 0; di < 4; di++) {
        atomicAdd(&ssum[di * 16 + tx], ls[di]);
        atomicAdd(&ssq[di * 16 + tx], ls2[di]);
    }
    __syncthreads();
    if (tid < 64) {
        atomicAdd(&g_bnstats[tid], ssum[tid]);
        atomicAdd(&g_bnstats[64 + tid], ssq[tid]);
    }
}

// ---------------- outer BN apply ----------------
__global__ void __launch_bounds__(256) bn_apply_kernel(const float* __restrict__ hin,
                                                       float* __restrict__ hout,
                                                       const float* __restrict__ gamma,
                                                       const float* __restrict__ beta,
                                                       int Mn, int doRelu) {
    const int start = blockIdx.x * 256 + threadIdx.x;
    const int stride = gridDim.x * 256;
    const int d = start & 63;
    const float invN = 1.f / (float)Mn;
    const float mean = g_bnstats[d] * invN;
    const float var = g_bnstats[64 + d] * invN - mean * mean;
    const float scale = gamma[d] * rsqrtf(var + 1e-5f);
    const float shift = beta[d] - mean * scale;
    for (int idx = start; idx < Mn * 64; idx += stride) {
        float v = hin[idx] * scale + shift;
        if (doRelu) v = fmaxf(v, 0.f);
        hout[idx] = v;
    }
}

// ---------------- launch ----------------
extern "C" void kernel_launch(void* const* d_in, const int* in_sizes, int n_in,
                              void* d_out, int out_size) {
    const float* atom_x = (const float*)d_in[0];
    const int* atom_feature = (const int*)d_in[1];
    const int* edge_index = (const int*)d_in[2];
    const float* edge_attr = (const float*)d_in[3];
    const float* atom_emb = (const float*)d_in[4];
    const float* proj_W = (const float*)d_in[5];
    const float* proj_b = (const float*)d_in[6];
    const float* lin_W = (const float*)d_in[7];
    const float* lin_b = (const float*)d_in[8];
    const float* root_emb = (const float*)d_in[9];
    const float* bond_W = (const float*)d_in[10];
    const float* bond_b = (const float*)d_in[11];
    const float* bond_g = (const float*)d_in[12];
    const float* bond_beta = (const float*)d_in[13];
    const float* gru_Wih = (const float*)d_in[14];
    const float* gru_bih = (const float*)d_in[15];
    const float* gru_Whh = (const float*)d_in[16];
    const float* gru_bhh = (const float*)d_in[17];
    const float* bn_g = (const float*)d_in[18];
    const float* bn_b = (const float*)d_in[19];
    const int* rowI = edge_index;
    const int* colI = edge_index + EE;
    float* out = (float*)d_out;

    float *p_cat, *p_h, *p_x, *p_deg, *p_stats, *p_bnstats, *p_wpack;
    int *p_cnt, *p_cntR;
    cudaGetSymbolAddress((void**)&p_cat, g_cat);
    cudaGetSymbolAddress((void**)&p_h, g_h);
    cudaGetSymbolAddress((void**)&p_x, g_x);
    cudaGetSymbolAddress((void**)&p_deg, g_deg);
    cudaGetSymbolAddress((void**)&p_stats, g_stats);
    cudaGetSymbolAddress((void**)&p_bnstats, g_bnstats);
    cudaGetSymbolAddress((void**)&p_cnt, g_cnt);
    cudaGetSymbolAddress((void**)&p_cntR, g_cntR);
    cudaGetSymbolAddress((void**)&p_wpack, g_wpack);

    static int smemSet = 0;
    const int gruSmem = (2 * 64 * 68 + 2 * 64 * 196 + 128) * 4;
    if (!smemSet) {
        cudaFuncSetAttribute(grumma_kernel, cudaFuncAttributeMaxDynamicSharedMemorySize,
                             gruSmem);
        smemSet = 1;
    }

    const int nScanBlocks = (NN + 1023) / 1024;

    zero_kernel<<<1, 256>>>(p_stats, 152);
    zeroi_kernel<<<256, 256>>>(p_cnt, NN);
    zeroi_kernel<<<256, 256>>>(p_cntR, NN);
    count_kernel<<<1024, 256>>>(rowI, colI);
    finalize_deg_kernel<<<256, 256>>>();
    scan1_kernel<<<nScanBlocks, 256>>>();
    scan2_kernel<<<1, 32>>>(nScanBlocks);
    scan3_kernel<<<256, 256>>>();
    fill_kernel<<<1024, 256>>>(rowI, colI, edge_attr);
    stats_kernel<<<296, 256>>>(edge_attr);
    packw_kernel<<<144, 256>>>(gru_Wih, gru_Whh);

    encoder_kernel<<<1024, 256>>>(atom_x, atom_feature, atom_emb);
    gemm_kernel<128><<<1563, 256>>>(p_cat, proj_W, proj_b, p_h, NN);

    for (int l = 0; l < 3; l++) {
        gemm_kernel<64><<<1563, 256>>>(p_h, lin_W + l * 64 * 64, lin_b + l * 64, p_x, NN);
        bondprep_kernel<<<1, 64>>>(bond_W + l * 16 * 64, bond_b + l * 64, bond_g + l * 64,
                                   bond_beta + l * 64);
        gather_kernel<<<(NN + 15) / 16, 256>>>();
        zero_kernel<<<1, 128>>>(p_bnstats, 128);
        grumma_kernel<<<1563, 256, gruSmem>>>(gru_bih + l * 192, gru_bhh + l * 192,
                                              root_emb + l * 64,
                                              p_wpack + (size_t)(l * 2 + 0) * 24576,
                                              p_wpack + (size_t)(l * 2 + 1) * 24576, NN);
        bn_apply_kernel<<<512, 256>>>(p_h, (l == 2) ? out : p_h, bn_g + l * 64, bn_b + l * 64,
                                      NN, (l < 2) ? 1 : 0);
    }
}

// round 6
// speedup vs baseline: 1.7608x; 1.0432x over previous
#include <cuda_runtime.h>
#include <math.h>

#define NN 100000
#define EE 1600000

// ---------------- scratch (device globals) ----------------
__device__ float g_h[NN * 64];
__device__ float g_x[NN * 64];
__device__ float g_aggr[NN * 64];
__device__ float g_deg[NN];
__device__ float g_dinv[NN];
__device__ float g_stats[152];
__device__ float g_Wp[16 * 64];
__device__ float g_bp[64];
__device__ float g_bnstats[128];
__device__ float g_bnscale[64];
__device__ float g_bnshift[64];
// packed tf32 hi/lo W fragments
__device__ float g_wpack[3 * 2 * 24 * 8 * 32 * 4];   // GRU: [l][which][nt24][ks8][lane][4]
__device__ float g_wlin[3 * 8 * 8 * 32 * 4];         // lin: [l][nt8][ks8][lane][4]
__device__ float g_wproj[8 * 16 * 32 * 4];           // proj: [nt8][ks16][lane][4]
// CSR by destination (col), with permuted payloads
__device__ int g_cntR[NN];
__device__ int g_cnt[NN];
__device__ int g_coff[NN + 1];
__device__ int g_cur[NN];
__device__ int g_bsum[128];
__device__ int g_erow[EE];
__device__ float g_nrm[EE];
__device__ float g_eattrp[EE * 16];

// ---------------- tf32 helpers ----------------
__device__ __forceinline__ unsigned f2tf32(float v) {
    unsigned r;
    asm("cvt.rna.tf32.f32 %0, %1;" : "=r"(r) : "f"(v));
    return r;
}
__device__ __forceinline__ void mma_tf32(float* c, unsigned a0, unsigned a1, unsigned a2,
                                         unsigned a3, unsigned b0, unsigned b1) {
    asm("mma.sync.aligned.m16n8k8.row.col.f32.tf32.tf32.f32 "
        "{%0,%1,%2,%3}, {%4,%5,%6,%7}, {%8,%9}, {%0,%1,%2,%3};"
        : "+f"(c[0]), "+f"(c[1]), "+f"(c[2]), "+f"(c[3])
        : "r"(a0), "r"(a1), "r"(a2), "r"(a3), "r"(b0), "r"(b1));
}

// shared mma core: As (pitch P), KT k-steps, N=64 out, 8 warps
template <int KT, int P>
__device__ __forceinline__ void mma_gemm_store(const float* As, const float* __restrict__ wpack,
                                               const float* __restrict__ bias,
                                               float* __restrict__ C, int M, int rowBase,
                                               int w, int lane) {
    const int mrow = w & 3;
    const int nhalf = w >> 2;
    const int g = lane >> 2, tg = lane & 3;
    float accs[4][4];
#pragma unroll
    for (int j = 0; j < 4; j++)
#pragma unroll
        for (int q = 0; q < 4; q++) accs[j][q] = 0.f;

#pragma unroll
    for (int ks = 0; ks < KT; ks++) {
        const int k0 = ks * 8;
        const float af[4] = {As[(mrow * 16 + g) * P + k0 + tg],
                             As[(mrow * 16 + g + 8) * P + k0 + tg],
                             As[(mrow * 16 + g) * P + k0 + tg + 4],
                             As[(mrow * 16 + g + 8) * P + k0 + tg + 4]};
        unsigned ah[4], al[4];
#pragma unroll
        for (int q = 0; q < 4; q++) {
            ah[q] = f2tf32(af[q]);
            al[q] = f2tf32(af[q] - __uint_as_float(ah[q]));
        }
#pragma unroll
        for (int j = 0; j < 4; j++) {
            const int nt = nhalf * 4 + j;
            const float4 b = __ldg(
                reinterpret_cast<const float4*>(&wpack[(((size_t)nt * KT + ks) * 32 + lane) * 4]));
            const unsigned bh0 = __float_as_uint(b.x);
            const unsigned bh4 = __float_as_uint(b.y);
            const unsigned bl0 = __float_as_uint(b.z);
            const unsigned bl4 = __float_as_uint(b.w);
            mma_tf32(accs[j], ah[0], ah[1], ah[2], ah[3], bh0, bh4);
            mma_tf32(accs[j], al[0], al[1], al[2], al[3], bh0, bh4);
            mma_tf32(accs[j], ah[0], ah[1], ah[2], ah[3], bl0, bl4);
        }
    }
#pragma unroll
    for (int j = 0; j < 4; j++) {
        const int n0 = (nhalf * 4 + j) * 8 + tg * 2;
        const float2 bv = make_float2(__ldg(&bias[n0]), __ldg(&bias[n0 + 1]));
        const int r0 = rowBase + mrow * 16 + g;
        if (r0 < M)
            *reinterpret_cast<float2*>(&C[(size_t)r0 * 64 + n0]) =
                make_float2(accs[j][0] + bv.x, accs[j][1] + bv.y);
        if (r0 + 8 < M)
            *reinterpret_cast<float2*>(&C[(size_t)(r0 + 8) * 64 + n0]) =
                make_float2(accs[j][2] + bv.x, accs[j][3] + bv.y);
    }
}

// ---------------- utility ----------------
__global__ void zero_kernel(float* __restrict__ p, int n) {
    int i = blockIdx.x * blockDim.x + threadIdx.x;
    int s = gridDim.x * blockDim.x;
    for (; i < n; i += s) p[i] = 0.f;
}
__global__ void zeroi_kernel(int* __restrict__ p, int n) {
    int i = blockIdx.x * blockDim.x + threadIdx.x;
    int s = gridDim.x * blockDim.x;
    for (; i < n; i += s) p[i] = 0;
}

// ---------------- pack GRU W hi/lo fragments ----------------
__global__ void packw_kernel(const float* __restrict__ Wih, const float* __restrict__ Whh) {
    const int l = blockIdx.x / 48;
    const int rem = blockIdx.x % 48;
    const int which = rem / 24;
    const int nt = rem % 24;
    const float* W = (which == 0 ? Wih : Whh) + (size_t)l * 192 * 64;
    const int ks = threadIdx.x >> 5;
    const int t = threadIdx.x & 31;
    const int g = t >> 2, tg = t & 3;
    const int n = nt * 8 + g;
    const int k0 = ks * 8 + tg;
    const float w0 = W[n * 64 + k0];
    const float w4 = W[n * 64 + k0 + 4];
    const unsigned h0 = f2tf32(w0), h4 = f2tf32(w4);
    float4 o;
    o.x = __uint_as_float(h0);
    o.y = __uint_as_float(h4);
    o.z = __uint_as_float(f2tf32(w0 - __uint_as_float(h0)));
    o.w = __uint_as_float(f2tf32(w4 - __uint_as_float(h4)));
    const size_t base = (((size_t)(l * 2 + which) * 24 + nt) * 8 + ks) * 32 + t;
    *reinterpret_cast<float4*>(&g_wpack[base * 4]) = o;
}

// ---------------- pack lin (3 layers, W transposed) ----------------
__global__ void packlin_kernel(const float* __restrict__ linW) {
    const int idx = blockIdx.x * 256 + threadIdx.x;  // 6144
    if (idx >= 3 * 8 * 8 * 32) return;
    const int l = idx / 2048;
    const int r1 = idx % 2048;
    const int nt = r1 / 256;
    const int r2 = r1 % 256;
    const int ks = r2 / 32;
    const int lane = r2 % 32;
    const int g = lane >> 2, tg = lane & 3;
    const int n = nt * 8 + g;
    const int k0 = ks * 8 + tg;
    const float* W = linW + (size_t)l * 4096;
    const float w0 = W[k0 * 64 + n];
    const float w4 = W[(k0 + 4) * 64 + n];
    const unsigned h0 = f2tf32(w0), h4 = f2tf32(w4);
    float4 o;
    o.x = __uint_as_float(h0);
    o.y = __uint_as_float(h4);
    o.z = __uint_as_float(f2tf32(w0 - __uint_as_float(h0)));
    o.w = __uint_as_float(f2tf32(w4 - __uint_as_float(h4)));
    *reinterpret_cast<float4*>(&g_wlin[(size_t)idx * 4]) = o;
}

// ---------------- pack proj (W transposed, K=128) ----------------
__global__ void packproj_kernel(const float* __restrict__ projW) {
    const int idx = blockIdx.x * 256 + threadIdx.x;  // 4096
    if (idx >= 8 * 16 * 32) return;
    const int nt = idx / 512;
    const int r = idx % 512;
    const int ks = r / 32;
    const int lane = r % 32;
    const int g = lane >> 2, tg = lane & 3;
    const int n = nt * 8 + g;
    const int k0 = ks * 8 + tg;
    const float w0 = projW[k0 * 64 + n];
    const float w4 = projW[(k0 + 4) * 64 + n];
    const unsigned h0 = f2tf32(w0), h4 = f2tf32(w4);
    float4 o;
    o.x = __uint_as_float(h0);
    o.y = __uint_as_float(h4);
    o.z = __uint_as_float(f2tf32(w0 - __uint_as_float(h0)));
    o.w = __uint_as_float(f2tf32(w4 - __uint_as_float(h4)));
    *reinterpret_cast<float4*>(&g_wproj[(size_t)idx * 4]) = o;
}

// ---------------- combined degree(row) + count(col) ----------------
__global__ void count_kernel(const int* __restrict__ rowI, const int* __restrict__ colI) {
    int s = gridDim.x * blockDim.x;
    for (int e = blockIdx.x * blockDim.x + threadIdx.x; e < EE; e += s) {
        atomicAdd(&g_cntR[rowI[e]], 1);
        atomicAdd(&g_cnt[colI[e]], 1);
    }
}
__global__ void finalize_deg_kernel() {
    int s = gridDim.x * blockDim.x;
    for (int n = blockIdx.x * blockDim.x + threadIdx.x; n < NN; n += s) {
        float dv = (float)g_cntR[n] + 1.f;
        g_deg[n] = dv;
        g_dinv[n] = rsqrtf(dv);
    }
}

// ---------------- CSR scan ----------------
__global__ void __launch_bounds__(256) scan1_kernel() {
    __shared__ int wsum[8];
    const int b = blockIdx.x;
    const int base = b * 1024;
    const int t = threadIdx.x;
    const int lane = t & 31, w = t >> 5;
    int v[4];
    const int idx0 = base + t * 4;
#pragma unroll
    for (int i = 0; i < 4; i++) {
        const int ii = idx0 + i;
        v[i] = (ii < NN) ? g_cnt[ii] : 0;
    }
    const int local = v[0] + v[1] + v[2] + v[3];
    int x = local;
#pragma unroll
    for (int off = 1; off < 32; off <<= 1) {
        int y = __shfl_up_sync(0xffffffffu, x, off);
        if (lane >= off) x += y;
    }
    if (lane == 31) wsum[w] = x;
    __syncthreads();
    if (t == 0) {
        int s = 0;
#pragma unroll
        for (int i = 0; i < 8; i++) { int tmp = wsum[i]; wsum[i] = s; s += tmp; }
        g_bsum[b] = s;
    }
    __syncthreads();
    int run = x - local + wsum[w];
#pragma unroll
    for (int i = 0; i < 4; i++) {
        const int ii = idx0 + i;
        if (ii < NN) g_coff[ii] = run;
        run += v[i];
    }
}
__global__ void scan2_kernel(int nb) {
    if (threadIdx.x == 0 && blockIdx.x == 0) {
        int s = 0;
        for (int i = 0; i < nb; i++) { int t = g_bsum[i]; g_bsum[i] = s; s += t; }
    }
}
__global__ void scan3_kernel() {
    int i = blockIdx.x * blockDim.x + threadIdx.x;
    int s = gridDim.x * blockDim.x;
    for (; i < NN; i += s) {
        const int vv = g_coff[i] + g_bsum[i >> 10];
        g_coff[i] = vv;
        g_cur[i] = vv;
    }
    if (blockIdx.x == 0 && threadIdx.x == 0) g_coff[NN] = EE;
}

// ---------------- fill: permute payloads into CSR order ----------------
__global__ void fill_kernel(const int* __restrict__ rowI, const int* __restrict__ colI,
                            const float* __restrict__ eattr) {
    int s = gridDim.x * blockDim.x;
    for (int e = blockIdx.x * blockDim.x + threadIdx.x; e < EE; e += s) {
        const int c = colI[e];
        const int r = rowI[e];
        const int pos = atomicAdd(&g_cur[c], 1);
        g_erow[pos] = r;
        g_nrm[pos] = g_dinv[r] * g_dinv[c];
        const float4* src = reinterpret_cast<const float4*>(eattr + (size_t)e * 16);
        float4* dst = reinterpret_cast<float4*>(g_eattrp + (size_t)pos * 16);
        dst[0] = __ldg(&src[0]);
        dst[1] = __ldg(&src[1]);
        dst[2] = __ldg(&src[2]);
        dst[3] = __ldg(&src[3]);
    }
}

// ---------------- edge-attr second-moment stats ----------------
__global__ void __launch_bounds__(256) stats_kernel(const float* __restrict__ eattr) {
    const int tid = threadIdx.x;
    const int parity = tid & 1;
    const int pair0 = (blockIdx.x * 256 + tid) >> 1;
    const int npairs = (gridDim.x * 256) >> 1;
    float sAcc[68];
    float mAcc[8];
#pragma unroll
    for (int i = 0; i < 68; i++) sAcc[i] = 0.f;
#pragma unroll
    for (int i = 0; i < 8; i++) mAcc[i] = 0.f;

    for (int e = pair0; e < EE; e += npairs) {
        const float4* ap = reinterpret_cast<const float4*>(eattr + (size_t)e * 16);
        float4 v0 = __ldg(&ap[0]), v1 = __ldg(&ap[1]), v2 = __ldg(&ap[2]), v3 = __ldg(&ap[3]);
        float a[16];
        a[0]=v0.x; a[1]=v0.y; a[2]=v0.z; a[3]=v0.w;
        a[4]=v1.x; a[5]=v1.y; a[6]=v1.z; a[7]=v1.w;
        a[8]=v2.x; a[9]=v2.y; a[10]=v2.z; a[11]=v2.w;
        a[12]=v3.x; a[13]=v3.y; a[14]=v3.z; a[15]=v3.w;
#pragma unroll
        for (int i = 0; i < 16; i++)
            if ((i >> 3) == parity) mAcc[i & 7] += a[i];
        int p = 0;
#pragma unroll
        for (int k = 0; k < 16; k++)
#pragma unroll
            for (int l = k; l < 16; l++) {
                if ((p & 1) == parity) sAcc[p >> 1] += a[k] * a[l];
                p++;
            }
    }
#pragma unroll
    for (int off = 16; off >= 2; off >>= 1) {
#pragma unroll
        for (int i = 0; i < 68; i++) sAcc[i] += __shfl_down_sync(0xffffffffu, sAcc[i], off);
#pragma unroll
        for (int i = 0; i < 8; i++) mAcc[i] += __shfl_down_sync(0xffffffffu, mAcc[i], off);
    }
    const int lane = tid & 31;
    if (lane < 2) {
#pragma unroll
        for (int i = 0; i < 68; i++) atomicAdd(&g_stats[i * 2 + lane], sAcc[i]);
#pragma unroll
        for (int i = 0; i < 8; i++) atomicAdd(&g_stats[136 + lane * 8 + i], mAcc[i]);
    }
}

// ---------------- fold bond Linear + BatchNorm into W', b' ----------------
__global__ void bondprep_kernel(const float* __restrict__ Wl, const float* __restrict__ bl,
                                const float* __restrict__ gl, const float* __restrict__ betal) {
    const int j = threadIdx.x;
    const float invE = 1.f / (float)EE;
    float w[16];
#pragma unroll
    for (int k = 0; k < 16; k++) w[k] = Wl[k * 64 + j];
    float dot_mw = 0.f;
#pragma unroll
    for (int k = 0; k < 16; k++) dot_mw += (g_stats[136 + k] * invE) * w[k];
    float quad = 0.f;
    int p = 0;
#pragma unroll
    for (int k = 0; k < 16; k++)
#pragma unroll
        for (int l = k; l < 16; l++) {
            const float s = g_stats[p++] * invE;
            quad += (k == l ? w[k] * w[l] : 2.f * w[k] * w[l]) * s;
        }
    const float b = bl[j];
    const float mean = dot_mw + b;
    const float e2 = quad + 2.f * b * dot_mw + b * b;
    const float var = e2 - mean * mean;
    const float scale = gl[j] * rsqrtf(var + 1e-6f);
#pragma unroll
    for (int k = 0; k < 16; k++) g_Wp[k * 64 + j] = w[k] * scale;
    g_bp[j] = (b - mean) * scale + betal[j];
}

// ---------------- proj GEMM with fused atom encoder (tf32 mma) ----------------
__global__ void __launch_bounds__(256) proj_mma_kernel(const float* __restrict__ ax,
                                                       const int* __restrict__ feat,
                                                       const float* __restrict__ emb,
                                                       const float* __restrict__ bias, int M) {
    __shared__ float As[64 * 132];
    const int tid = threadIdx.x;
    const int rowBase = blockIdx.x * 64;
#pragma unroll
    for (int idx = tid; idx < 64 * 32; idx += 256) {
        const int r = idx >> 5;
        const int c4 = idx & 31;
        const int gr = rowBase + r;
        float4 v = make_float4(0.f, 0.f, 0.f, 0.f);
        if (gr < M) {
            if (c4 < 16) {
                v = __ldg(reinterpret_cast<const float4*>(&ax[(size_t)gr * 64 + c4 * 4]));
            } else {
                const int d = (c4 - 16) * 4;
#pragma unroll
                for (int f = 0; f < 9; f++) {
                    const int fv = __ldg(&feat[gr * 9 + f]);
                    const float4 ev =
                        __ldg(reinterpret_cast<const float4*>(&emb[(f * 16 + fv) * 64 + d]));
                    v.x += ev.x; v.y += ev.y; v.z += ev.z; v.w += ev.w;
                }
            }
        }
        *reinterpret_cast<float4*>(&As[r * 132 + c4 * 4]) = v;
    }
    __syncthreads();
    mma_gemm_store<16, 132>(As, g_wproj, bias, g_h, M, rowBase, tid >> 5, tid & 31);
}

// ---------------- lin GEMM (tf32 mma), optional fused BN+relu on A ----------------
template <int MODE>  // 0 plain, 1 BN(scale/shift)+relu
__global__ void __launch_bounds__(256) lin_mma_kernel(const float* __restrict__ H,
                                                      const float* __restrict__ wpack,
                                                      const float* __restrict__ bias, int M) {
    __shared__ float As[64 * 68];
    const int tid = threadIdx.x;
    const int rowBase = blockIdx.x * 64;
#pragma unroll
    for (int idx = tid; idx < 64 * 16; idx += 256) {
        const int r = idx >> 4;
        const int c4 = idx & 15;
        const int gr = rowBase + r;
        float4 v = make_float4(0.f, 0.f, 0.f, 0.f);
        if (gr < M) {
            v = *reinterpret_cast<const float4*>(&H[(size_t)gr * 64 + c4 * 4]);
            if (MODE == 1) {
                const int d = c4 * 4;
                v.x = fmaxf(v.x * g_bnscale[d + 0] + g_bnshift[d + 0], 0.f);
                v.y = fmaxf(v.y * g_bnscale[d + 1] + g_bnshift[d + 1], 0.f);
                v.z = fmaxf(v.z * g_bnscale[d + 2] + g_bnshift[d + 2], 0.f);
                v.w = fmaxf(v.w * g_bnscale[d + 3] + g_bnshift[d + 3], 0.f);
            }
        }
        *reinterpret_cast<float4*>(&As[r * 68 + c4 * 4]) = v;
    }
    __syncthreads();
    mma_gemm_store<8, 68>(As, wpack, bias, g_x, M, rowBase, tid >> 5, tid & 31);
}

// ---------------- CSR gather ----------------
__global__ void __launch_bounds__(256) gather_kernel() {
    const int tid = threadIdx.x;
    const int t = tid & 15;
    const int nloc = tid >> 4;
    const int n = blockIdx.x * 16 + nloc;
    float4 wreg[16];
#pragma unroll
    for (int k = 0; k < 16; k++)
        wreg[k] = *reinterpret_cast<const float4*>(&g_Wp[k * 64 + t * 4]);
    const float4 bb = *reinterpret_cast<const float4*>(&g_bp[t * 4]);
    if (n >= NN) return;
    const int jb = g_coff[n];
    const int je = g_coff[n + 1];
    float4 acc = make_float4(0.f, 0.f, 0.f, 0.f);
    for (int j = jb; j < je; j++) {
        const int r = __ldg(&g_erow[j]);
        const float nrm = __ldg(&g_nrm[j]);
        const float4* ap = reinterpret_cast<const float4*>(g_eattrp + (size_t)j * 16);
        float4 m = bb;
#pragma unroll
        for (int q = 0; q < 4; q++) {
            const float4 a = __ldg(&ap[q]);
            const float4 w0 = wreg[4 * q + 0];
            const float4 w1 = wreg[4 * q + 1];
            const float4 w2 = wreg[4 * q + 2];
            const float4 w3 = wreg[4 * q + 3];
            m.x = fmaf(a.x, w0.x, fmaf(a.y, w1.x, fmaf(a.z, w2.x, fmaf(a.w, w3.x, m.x))));
            m.y = fmaf(a.x, w0.y, fmaf(a.y, w1.y, fmaf(a.z, w2.y, fmaf(a.w, w3.y, m.y))));
            m.z = fmaf(a.x, w0.z, fmaf(a.y, w1.z, fmaf(a.z, w2.z, fmaf(a.w, w3.z, m.z))));
            m.w = fmaf(a.x, w0.w, fmaf(a.y, w1.w, fmaf(a.z, w2.w, fmaf(a.w, w3.w, m.w))));
        }
        const float4 xv = __ldg(reinterpret_cast<const float4*>(&g_x[(size_t)r * 64 + t * 4]));
        acc.x = fmaf(nrm, fmaxf(m.x + xv.x, 0.f), acc.x);
        acc.y = fmaf(nrm, fmaxf(m.y + xv.y, 0.f), acc.y);
        acc.z = fmaf(nrm, fmaxf(m.z + xv.z, 0.f), acc.z);
        acc.w = fmaf(nrm, fmaxf(m.w + xv.w, 0.f), acc.w);
    }
    *reinterpret_cast<float4*>(&g_aggr[(size_t)n * 64 + t * 4]) = acc;
}

// ---------------- fused GRU with tf32 HMMA (3xTF32) ----------------
__global__ void __launch_bounds__(256, 1) grumma_kernel(
    const float* __restrict__ bih, const float* __restrict__ bhh,
    const float* __restrict__ root, const float* __restrict__ wpackI,
    const float* __restrict__ wpackH, int M) {
    extern __shared__ float smem[];
    float* Aag = smem;
    float* Ax = Aag + 64 * 68;
    float* Sgi = Ax + 64 * 68;
    float* Sgh = Sgi + 64 * 196;
    float* ssum = Sgh + 64 * 196;
    float* ssq = ssum + 64;

    const int tid = threadIdx.x;
    const int w = tid >> 5;
    const int lane = tid & 31;
    const int rowBase = blockIdx.x * 64;

#pragma unroll
    for (int idx = tid; idx < 64 * 16; idx += 256) {
        const int r = idx >> 4;
        const int c4 = idx & 15;
        const int gr = rowBase + r;
        float4 va = make_float4(0.f, 0.f, 0.f, 0.f);
        float4 vx = make_float4(0.f, 0.f, 0.f, 0.f);
        if (gr < M) {
            va = *reinterpret_cast<const float4*>(&g_aggr[(size_t)gr * 64 + c4 * 4]);
            vx = *reinterpret_cast<const float4*>(&g_x[(size_t)gr * 64 + c4 * 4]);
        }
        *reinterpret_cast<float4*>(&Aag[r * 68 + c4 * 4]) = va;
        *reinterpret_cast<float4*>(&Ax[r * 68 + c4 * 4]) = vx;
    }
    if (tid < 64) { ssum[tid] = 0.f; ssq[tid] = 0.f; }
    __syncthreads();

    const int mrow = w & 3;
    const int ntbase = (w >> 2) * 12;
    const int g = lane >> 2, tg = lane & 3;

#pragma unroll
    for (int which = 0; which < 2; which++) {
        const float* A = (which == 0) ? Aag : Ax;
        const float* wp = (which == 0) ? wpackI : wpackH;
        float* S = (which == 0) ? Sgi : Sgh;

        float accs[12][4];
#pragma unroll
        for (int j = 0; j < 12; j++)
#pragma unroll
            for (int q = 0; q < 4; q++) accs[j][q] = 0.f;

#pragma unroll
        for (int ks = 0; ks < 8; ks++) {
            const int k0 = ks * 8;
            const float af[4] = {A[(mrow * 16 + g) * 68 + k0 + tg],
                                 A[(mrow * 16 + g + 8) * 68 + k0 + tg],
                                 A[(mrow * 16 + g) * 68 + k0 + tg + 4],
                                 A[(mrow * 16 + g + 8) * 68 + k0 + tg + 4]};
            unsigned ah[4], al[4];
#pragma unroll
            for (int q = 0; q < 4; q++) {
                ah[q] = f2tf32(af[q]);
                al[q] = f2tf32(af[q] - __uint_as_float(ah[q]));
            }
#pragma unroll
            for (int j = 0; j < 12; j++) {
                const int nt = ntbase + j;
                const float4 b =
                    __ldg(reinterpret_cast<const float4*>(&wp[(((size_t)nt * 8 + ks) * 32 + lane) * 4]));
                const unsigned bh0 = __float_as_uint(b.x);
                const unsigned bh4 = __float_as_uint(b.y);
                const unsigned bl0 = __float_as_uint(b.z);
                const unsigned bl4 = __float_as_uint(b.w);
                mma_tf32(accs[j], ah[0], ah[1], ah[2], ah[3], bh0, bh4);
                mma_tf32(accs[j], al[0], al[1], al[2], al[3], bh0, bh4);
                mma_tf32(accs[j], ah[0], ah[1], ah[2], ah[3], bl0, bl4);
            }
        }
#pragma unroll
        for (int j = 0; j < 12; j++) {
            const int n0 = (ntbase + j) * 8;
            const int r0 = mrow * 16 + g;
            *reinterpret_cast<float2*>(&S[r0 * 196 + n0 + tg * 2]) =
                make_float2(accs[j][0], accs[j][1]);
            *reinterpret_cast<float2*>(&S[(r0 + 8) * 196 + n0 + tg * 2]) =
                make_float2(accs[j][2], accs[j][3]);
        }
    }
    __syncthreads();

    const int tx = tid & 15;
    const int ty = tid >> 4;
    float ls[4] = {0.f, 0.f, 0.f, 0.f};
    float ls2[4] = {0.f, 0.f, 0.f, 0.f};
#pragma unroll
    for (int ri = 0; ri < 4; ri++) {
        const int r = ty * 4 + ri;
        const int row = rowBase + r;
        if (row < M) {
            const float dg = __ldg(&g_deg[row]);
#pragma unroll
            for (int di = 0; di < 4; di++) {
                const int d = di * 16 + tx;
                const float ir = Sgi[r * 196 + d] + __ldg(&bih[d]);
                const float iz = Sgi[r * 196 + 64 + d] + __ldg(&bih[64 + d]);
                const float inn = Sgi[r * 196 + 128 + d] + __ldg(&bih[128 + d]);
                const float hr = Sgh[r * 196 + d] + __ldg(&bhh[d]);
                const float hz = Sgh[r * 196 + 64 + d] + __ldg(&bhh[64 + d]);
                const float hn = Sgh[r * 196 + 128 + d] + __ldg(&bhh[128 + d]);
                const float xv = Ax[r * 68 + d];
                const float rr = 1.f / (1.f + expf(-(ir + hr)));
                const float z = 1.f / (1.f + expf(-(iz + hz)));
                const float nn2 = tanhf(inn + rr * hn);
                const float upd = (1.f - z) * nn2 + z * xv;
                const float hl = upd + fmaxf(xv + __ldg(&root[d]), 0.f) / dg;
                g_h[(size_t)row * 64 + d] = hl;
                ls[di] += hl;
                ls2[di] += hl * hl;
            }
        }
    }
#pragma unroll
    for (int di = 0; di < 4; di++) {
        atomicAdd(&ssum[di * 16 + tx], ls[di]);
        atomicAdd(&ssq[di * 16 + tx], ls2[di]);
    }
    __syncthreads();
    if (tid < 64) {
        atomicAdd(&g_bnstats[tid], ssum[tid]);
        atomicAdd(&g_bnstats[64 + tid], ssq[tid]);
    }
}

// ---------------- finalize BN stats -> scale/shift ----------------
__global__ void bnfin_kernel(const float* __restrict__ gamma, const float* __restrict__ beta) {
    const int d = threadIdx.x;  // 64
    const float invN = 1.f / (float)NN;
    const float mean = g_bnstats[d] * invN;
    const float var = g_bnstats[64 + d] * invN - mean * mean;
    const float sc = gamma[d] * rsqrtf(var + 1e-5f);
    g_bnscale[d] = sc;
    g_bnshift[d] = beta[d] - mean * sc;
}

// ---------------- final output: BN apply (no relu) ----------------
__global__ void __launch_bounds__(256) bnout_kernel(float* __restrict__ out) {
    const int start = blockIdx.x * 256 + threadIdx.x;
    const int stride = gridDim.x * 256;
    for (int idx = start; idx < NN * 64; idx += stride) {
        const int d = idx & 63;
        out[idx] = g_h[idx] * g_bnscale[d] + g_bnshift[d];
    }
}

// ---------------- launch ----------------
extern "C" void kernel_launch(void* const* d_in, const int* in_sizes, int n_in,
                              void* d_out, int out_size) {
    const float* atom_x = (const float*)d_in[0];
    const int* atom_feature = (const int*)d_in[1];
    const int* edge_index = (const int*)d_in[2];
    const float* edge_attr = (const float*)d_in[3];
    const float* atom_emb = (const float*)d_in[4];
    const float* proj_W = (const float*)d_in[5];
    const float* proj_b = (const float*)d_in[6];
    const float* lin_W = (const float*)d_in[7];
    const float* lin_b = (const float*)d_in[8];
    const float* root_emb = (const float*)d_in[9];
    const float* bond_W = (const float*)d_in[10];
    const float* bond_b = (const float*)d_in[11];
    const float* bond_g = (const float*)d_in[12];
    const float* bond_beta = (const float*)d_in[13];
    const float* gru_Wih = (const float*)d_in[14];
    const float* gru_bih = (const float*)d_in[15];
    const float* gru_Whh = (const float*)d_in[16];
    const float* gru_bhh = (const float*)d_in[17];
    const float* bn_g = (const float*)d_in[18];
    const float* bn_b = (const float*)d_in[19];
    const int* rowI = edge_index;
    const int* colI = edge_index + EE;
    float* out = (float*)d_out;

    float *p_stats, *p_bnstats, *p_wpack, *p_wlin;
    int *p_cnt, *p_cntR;
    cudaGetSymbolAddress((void**)&p_stats, g_stats);
    cudaGetSymbolAddress((void**)&p_bnstats, g_bnstats);
    cudaGetSymbolAddress((void**)&p_cnt, g_cnt);
    cudaGetSymbolAddress((void**)&p_cntR, g_cntR);
    cudaGetSymbolAddress((void**)&p_wpack, g_wpack);
    cudaGetSymbolAddress((void**)&p_wlin, g_wlin);

    static int smemSet = 0;
    const int gruSmem = (2 * 64 * 68 + 2 * 64 * 196 + 128) * 4;
    if (!smemSet) {
        cudaFuncSetAttribute(grumma_kernel, cudaFuncAttributeMaxDynamicSharedMemorySize,
                             gruSmem);
        smemSet = 1;
    }

    const int nScanBlocks = (NN + 1023) / 1024;

    zero_kernel<<<1, 256>>>(p_stats, 152);
    zeroi_kernel<<<256, 256>>>(p_cnt, NN);
    zeroi_kernel<<<256, 256>>>(p_cntR, NN);
    count_kernel<<<1024, 256>>>(rowI, colI);
    finalize_deg_kernel<<<256, 256>>>();
    scan1_kernel<<<nScanBlocks, 256>>>();
    scan2_kernel<<<1, 32>>>(nScanBlocks);
    scan3_kernel<<<256, 256>>>();
    fill_kernel<<<1024, 256>>>(rowI, colI, edge_attr);
    stats_kernel<<<296, 256>>>(edge_attr);
    packw_kernel<<<144, 256>>>(gru_Wih, gru_Whh);
    packlin_kernel<<<24, 256>>>(lin_W);
    packproj_kernel<<<16, 256>>>(proj_W);

    proj_mma_kernel<<<1563, 256>>>(atom_x, atom_feature, atom_emb, proj_b, NN);

    for (int l = 0; l < 3; l++) {
        if (l == 0) {
            float *p_h;
            cudaGetSymbolAddress((void**)&p_h, g_h);
            lin_mma_kernel<0><<<1563, 256>>>(p_h, p_wlin + (size_t)l * 8192, lin_b + l * 64, NN);
        } else {
            float *p_h;
            cudaGetSymbolAddress((void**)&p_h, g_h);
            lin_mma_kernel<1><<<1563, 256>>>(p_h, p_wlin + (size_t)l * 8192, lin_b + l * 64, NN);
        }
        bondprep_kernel<<<1, 64>>>(bond_W + l * 16 * 64, bond_b + l * 64, bond_g + l * 64,
                                   bond_beta + l * 64);
        gather_kernel<<<(NN + 15) / 16, 256>>>();
        zero_kernel<<<1, 128>>>(p_bnstats, 128);
        grumma_kernel<<<1563, 256, gruSmem>>>(gru_bih + l * 192, gru_bhh + l * 192,
                                              root_emb + l * 64,
                                              p_wpack + (size_t)(l * 2 + 0) * 24576,
                                              p_wpack + (size_t)(l * 2 + 1) * 24576, NN);
        bnfin_kernel<<<1, 64>>>(bn_g + l * 64, bn_b + l * 64);
    }
    bnout_kernel<<<512, 256>>>(out);
}